// round 4
// baseline (speedup 1.0000x reference)
#include <cuda_runtime.h>
#include <math.h>

#define HH 192
#define WW 192
#define HW (HH*WW)
#define NBATCH 6
#define KC 400
#define MM 403
#define NCOL 405
#define SRIDE 416
#define NB 64
#define LAMBDAV 100.0f
#define BIGV 1.0e8f
#define EPSV 1.0e-9f
#define STEPC (2.0f/191.0f)
#define HALF_LN2 0.34657359028f   // 0.5*ln(2): folded into TPS weights for log2f

// ---------------- device scratch ----------------
__device__ float g_A[NBATCH * MM * SRIDE];
__device__ float g_warp[NBATCH * 5 * HW];
__device__ float g_src[NBATCH * KC * 2];
__device__ float g_sol[NBATCH * MM * 2];
__device__ int   g_swaplist[NBATCH * 128];   // (src<<16)|dest pairs, per current panel
__device__ int   g_swapcount[NBATCH];

// ---------------- Stage 1: backward warp ----------------
__global__ void warp_kernel(const float* __restrict__ duv,
                            const float* __restrict__ uv,
                            float* __restrict__ outMask)
{
    int idx = blockIdx.x * blockDim.x + threadIdx.x;
    if (idx >= NBATCH * HW) return;
    int n = idx / HW;
    int p = idx - n * HW;

    float u = uv[idx * 2 + 0];
    float v = uv[idx * 2 + 1];
    float x = (u + 1.0f) * 0.5f * (float)(WW - 1);
    float y = (v + 1.0f) * 0.5f * (float)(HH - 1);
    float x0f = floorf(x), y0f = floorf(y);
    float wx = x - x0f, wy = y - y0f;
    int x0 = (int)x0f, y0 = (int)y0f;

    float w00 = (1.0f - wx) * (1.0f - wy);
    float w10 = wx * (1.0f - wy);
    float w01 = (1.0f - wx) * wy;
    float w11 = wx * wy;

    float acc0 = 0.f, acc1 = 0.f, acc2 = 0.f, acc3 = 0.f, acc4 = 0.f;

    const int dxs[4] = {0, 1, 0, 1};
    const int dys[4] = {0, 0, 1, 1};
    const float wts[4] = {w00, w10, w01, w11};

    #pragma unroll
    for (int c = 0; c < 4; ++c) {
        int xi = x0 + dxs[c];
        int yi = y0 + dys[c];
        if (xi >= 0 && xi < WW && yi >= 0 && yi < HH) {
            int q = yi * WW + xi;
            float dux = duv[q * 2 + 0];
            float duy = duv[q * 2 + 1];
            float val = (fabsf(dux) <= 1.0f && fabsf(duy) <= 1.0f) ? 1.0f : 0.0f;
            float gx = xi * STEPC - 1.0f;
            float gy = yi * STEPC - 1.0f;
            float w = wts[c];
            acc0 += gx * w;
            acc1 += gy * w;
            acc2 += (dux - gx) * val * w;
            acc3 += (duy - gy) * val * w;
            acc4 += val * w;
        }
    }

    float mk = (acc4 > 0.5f) ? 1.0f : 0.0f;
    float* Wp = g_warp + n * 5 * HW;
    Wp[0 * HW + p] = acc0;
    Wp[1 * HW + p] = acc1;
    Wp[2 * HW + p] = acc2;
    Wp[3 * HW + p] = acc3;
    Wp[4 * HW + p] = mk;
    outMask[idx] = mk;
}

// ---------------- Stage 2: build augmented TPS systems ----------------
__global__ void build_kernel()
{
    int n  = blockIdx.x;
    int rb = blockIdx.y;
    int tid = threadIdx.x;

    __shared__ float s_sx[KC], s_sy[KC], s_m[KC], s_dx[KC], s_dy[KC];

    const float* Wp = g_warp + n * 5 * HW;
    for (int k = tid; k < KC; k += blockDim.x) {
        int a = k / 20, b = k - a * 20;
        int ii = __double2int_rn(a * (191.0 / 19.0));
        int jj = __double2int_rn(b * (191.0 / 19.0));
        int p = ii * WW + jj;
        float sx = Wp[p];
        float sy = Wp[HW + p];
        float m  = Wp[4 * HW + p];
        s_sx[k] = sx; s_sy[k] = sy; s_m[k] = m;
        s_dx[k] = jj * STEPC - 1.0f;
        s_dy[k] = ii * STEPC - 1.0f;
        if (rb == 0) {
            g_src[(n * KC + k) * 2 + 0] = sx;
            g_src[(n * KC + k) * 2 + 1] = sy;
        }
    }
    __syncthreads();

    float* A = g_A + n * MM * SRIDE;
    int r0 = rb * 51;
    int r1 = min(MM, r0 + 51);
    for (int i = r0; i < r1; ++i) {
        for (int j = tid; j < NCOL; j += blockDim.x) {
            float vout;
            if (i < KC) {
                if (j < KC) {
                    float dx = s_sx[i] - s_sx[j];
                    float dy = s_sy[i] - s_sy[j];
                    float r2 = dx * dx + dy * dy;
                    vout = 0.5f * r2 * __logf(r2 + EPSV);
                    if (i == j) vout += LAMBDAV + BIGV * (1.0f - s_m[i]);
                } else if (j == 400) vout = 1.0f;
                else if (j == 401) vout = s_sx[i];
                else if (j == 402) vout = s_sy[i];
                else if (j == 403) vout = s_dx[i];
                else               vout = s_dy[i];
            } else {
                if (j < KC) {
                    vout = (i == 400) ? 1.0f : ((i == 401) ? s_sx[j] : s_sy[j]);
                } else {
                    vout = 0.0f;
                }
            }
            A[i * SRIDE + j] = vout;
        }
    }
}

// ---------------- Stage 3a: panel factorization (smem) + permutation list ----------------
__global__ void __launch_bounds__(1024, 1) panel_kernel(int k0, int nb)
{
    int n = blockIdx.x;
    int tid = threadIdx.x;
    int lane = tid & 31;
    int wid = tid >> 5;

    extern __shared__ float sP[];     // R x 65
    __shared__ int s_pvt[64];
    __shared__ int s_perm[448];

    float* A = g_A + n * MM * SRIDE;
    int R = MM - k0;

    for (int idx = tid; idx < R * nb; idx += 1024) {
        int r = idx / nb, c = idx - r * nb;
        sP[r * 65 + c] = A[(k0 + r) * SRIDE + k0 + c];
    }
    for (int r = tid; r < R; r += 1024) s_perm[r] = r;
    __syncthreads();

    for (int j = 0; j < nb; ++j) {
        if (wid == 0) {
            float best = -1.0f; int brow = j;
            for (int r = j + lane; r < R; r += 32) {
                float v = fabsf(sP[r * 65 + j]);
                if (v > best) { best = v; brow = r; }
            }
            #pragma unroll
            for (int off = 16; off > 0; off >>= 1) {
                float ov = __shfl_down_sync(0xffffffffu, best, off);
                int   orow = __shfl_down_sync(0xffffffffu, brow, off);
                if (ov > best) { best = ov; brow = orow; }
            }
            brow = __shfl_sync(0xffffffffu, brow, 0);
            if (brow != j) {
                for (int c = lane; c < nb; c += 32) {
                    float t = sP[j * 65 + c];
                    sP[j * 65 + c] = sP[brow * 65 + c];
                    sP[brow * 65 + c] = t;
                }
            }
            if (lane == 0) s_pvt[j] = brow;
        }
        __syncthreads();

        float pivinv = 1.0f / sP[j * 65 + j];
        for (int r = j + 1 + wid; r < R; r += 32) {
            float m = sP[r * 65 + j] * pivinv;
            for (int c = j + 1 + lane; c < nb; c += 32)
                sP[r * 65 + c] = fmaf(-m, sP[j * 65 + c], sP[r * 65 + c]);
            if (lane == 0) sP[r * 65 + j] = m;
        }
        __syncthreads();
    }

    // permutation pair list for trailing columns
    if (tid == 0) {
        for (int j = 0; j < nb; ++j) {
            int pj = s_pvt[j];
            int t = s_perm[j]; s_perm[j] = s_perm[pj]; s_perm[pj] = t;
        }
        int m = 0;
        for (int r = 0; r < R; ++r) {
            if (s_perm[r] != r) {
                g_swaplist[n * 128 + m] = (k0 + r) | ((k0 + s_perm[r]) << 16);
                ++m;
            }
        }
        g_swapcount[n] = m;
    }

    for (int idx = tid; idx < R * nb; idx += 1024) {
        int r = idx / nb, c = idx - r * nb;
        A[(k0 + r) * SRIDE + k0 + c] = sP[r * 65 + c];
    }
}

// ---------------- Stage 3b: fused swap + trisolve + GEMM for one column slab ----------------
// grid: (nslabs, NBATCH), 256 threads, dynamic smem: sw[128*65] + sL[64*65] + sB[64*65]
__global__ void __launch_bounds__(256, 1) fused_update(int k0, int nb)
{
    extern __shared__ float smem[];
    float* sw = smem;               // 128*65 : swap buffer / As tile
    float* sL = sw + 128 * 65;      // 64*65  : L11
    float* sB = sL + 64 * 65;       // 64*65  : U12 slab

    int n = blockIdx.y;
    float* A = g_A + n * MM * SRIDE;
    int col0 = k0 + nb + blockIdx.x * 64;
    int tid = threadIdx.x;
    int tx = tid & 63;
    int ty = tid >> 6;              // 4 row slots

    // --- Phase A: apply row permutation (two parallel passes) ---
    int m = g_swapcount[n];
    int c = col0 + tx;
    for (int s = ty; s < m; s += 4) {
        int pack = g_swaplist[n * 128 + s];
        int src = pack >> 16;
        if (c < NCOL) sw[s * 65 + tx] = A[src * SRIDE + c];
    }
    __syncthreads();
    for (int s = ty; s < m; s += 4) {
        int pack = g_swaplist[n * 128 + s];
        int dest = pack & 0xFFFF;
        if (c < NCOL) A[dest * SRIDE + c] = sw[s * 65 + tx];
    }
    __syncthreads();

    // --- Phase B: trisolve U12 = L11^-1 * A12 (slab columns) ---
    for (int idx = tid; idx < nb * nb; idx += 256) {
        int r = idx / nb, cc = idx - r * nb;
        sL[r * 65 + cc] = A[(k0 + r) * SRIDE + k0 + cc];
    }
    for (int idx = tid; idx < nb * 64; idx += 256) {
        int r = idx >> 6, cc = idx & 63;
        int gc = col0 + cc;
        sB[r * 65 + cc] = (gc < NCOL) ? A[(k0 + r) * SRIDE + gc] : 0.0f;
    }
    __syncthreads();
    for (int i = 0; i < nb - 1; ++i) {
        float bi = sB[i * 65 + tx];
        for (int jj = i + 1 + ty; jj < nb; jj += 4)
            sB[jj * 65 + tx] = fmaf(-sL[jj * 65 + i], bi, sB[jj * 65 + tx]);
        __syncthreads();
    }
    for (int idx = tid; idx < nb * 64; idx += 256) {
        int r = idx >> 6, cc = idx & 63;
        int gc = col0 + cc;
        if (gc < NCOL) A[(k0 + r) * SRIDE + gc] = sB[r * 65 + cc];
    }
    __syncthreads();

    // --- Phase C: A22 -= L21 * U12 over row tiles ---
    int r2 = MM - (k0 + nb);
    int tx4 = (tid & 15) * 4;       // col within slab
    int ty4 = (tid >> 4) * 4;       // row within tile
    for (int row0 = k0 + nb; row0 < MM; row0 += 64) {
        for (int idx = tid; idx < 64 * 64; idx += 256) {
            int a = idx >> 6, b = idx & 63;
            int r = row0 + a;
            sw[a * 65 + b] = (r < MM && b < nb) ? A[r * SRIDE + k0 + b] : 0.0f;
        }
        __syncthreads();

        float acc[4][4];
        #pragma unroll
        for (int i = 0; i < 4; ++i)
            #pragma unroll
            for (int j = 0; j < 4; ++j) acc[i][j] = 0.0f;

        for (int kk = 0; kk < nb; ++kk) {
            float a0 = sw[(ty4 + 0) * 65 + kk], a1 = sw[(ty4 + 1) * 65 + kk];
            float a2 = sw[(ty4 + 2) * 65 + kk], a3 = sw[(ty4 + 3) * 65 + kk];
            float b0 = sB[kk * 65 + tx4 + 0], b1 = sB[kk * 65 + tx4 + 1];
            float b2 = sB[kk * 65 + tx4 + 2], b3 = sB[kk * 65 + tx4 + 3];
            acc[0][0] = fmaf(a0, b0, acc[0][0]); acc[0][1] = fmaf(a0, b1, acc[0][1]);
            acc[0][2] = fmaf(a0, b2, acc[0][2]); acc[0][3] = fmaf(a0, b3, acc[0][3]);
            acc[1][0] = fmaf(a1, b0, acc[1][0]); acc[1][1] = fmaf(a1, b1, acc[1][1]);
            acc[1][2] = fmaf(a1, b2, acc[1][2]); acc[1][3] = fmaf(a1, b3, acc[1][3]);
            acc[2][0] = fmaf(a2, b0, acc[2][0]); acc[2][1] = fmaf(a2, b1, acc[2][1]);
            acc[2][2] = fmaf(a2, b2, acc[2][2]); acc[2][3] = fmaf(a2, b3, acc[2][3]);
            acc[3][0] = fmaf(a3, b0, acc[3][0]); acc[3][1] = fmaf(a3, b1, acc[3][1]);
            acc[3][2] = fmaf(a3, b2, acc[3][2]); acc[3][3] = fmaf(a3, b3, acc[3][3]);
        }

        #pragma unroll
        for (int i = 0; i < 4; ++i) {
            int r = row0 + ty4 + i;
            if (r >= MM) continue;
            #pragma unroll
            for (int j = 0; j < 4; ++j) {
                int gc = col0 + tx4 + j;
                if (gc < NCOL) A[r * SRIDE + gc] -= acc[i][j];
            }
        }
        __syncthreads();
    }
    (void)r2;
}

// ---------------- Stage 3c: blocked back-substitution ----------------
__global__ void __launch_bounds__(256) backsub_kernel()
{
    int n = blockIdx.x;
    int tid = threadIdx.x;
    int lane = tid & 31;
    int wid = tid >> 5;
    float* A = g_A + n * MM * SRIDE;

    __shared__ float sD[64 * 65];
    __shared__ float x0s[MM], x1s[MM];

    for (int j = tid; j < MM; j += 256) {
        x0s[j] = A[j * SRIDE + 403];
        x1s[j] = A[j * SRIDE + 404];
    }
    __syncthreads();

    for (int b = 6; b >= 0; --b) {
        int k0 = b * 64;
        int nb = (MM - k0 < 64) ? (MM - k0) : 64;

        for (int idx = tid; idx < nb * nb; idx += 256) {
            int r = idx / nb, cc = idx - r * nb;
            sD[r * 65 + cc] = A[(k0 + r) * SRIDE + k0 + cc];
        }
        __syncthreads();

        if (wid == 0) {
            for (int k = nb - 1; k >= 0; --k) {
                float s0 = 0.f, s1 = 0.f;
                for (int j = k + 1 + lane; j < nb; j += 32) {
                    float u = sD[k * 65 + j];
                    s0 = fmaf(u, x0s[k0 + j], s0);
                    s1 = fmaf(u, x1s[k0 + j], s1);
                }
                #pragma unroll
                for (int off = 16; off > 0; off >>= 1) {
                    s0 += __shfl_down_sync(0xffffffffu, s0, off);
                    s1 += __shfl_down_sync(0xffffffffu, s1, off);
                }
                if (lane == 0) {
                    float d = 1.0f / sD[k * 65 + k];
                    x0s[k0 + k] = (x0s[k0 + k] - s0) * d;
                    x1s[k0 + k] = (x1s[k0 + k] - s1) * d;
                }
                __syncwarp();
            }
        }
        __syncthreads();

        for (int r = tid; r < k0; r += 256) {
            float s0 = 0.f, s1 = 0.f;
            const float* Ur = A + r * SRIDE + k0;
            #pragma unroll 8
            for (int j = 0; j < nb; ++j) {
                float u = Ur[j];
                s0 = fmaf(u, x0s[k0 + j], s0);
                s1 = fmaf(u, x1s[k0 + j], s1);
            }
            x0s[r] -= s0;
            x1s[r] -= s1;
        }
        __syncthreads();
    }

    for (int j = tid; j < MM; j += 256) {
        g_sol[(n * MM + j) * 2 + 0] = x0s[j];
        g_sol[(n * MM + j) * 2 + 1] = x1s[j];
    }
}

// ---------------- Stage 4: TPS evaluation + Jacobian + output ----------------
__global__ void __launch_bounds__(256) eval_kernel(float* __restrict__ outDef)
{
    int n = blockIdx.y;
    int p = blockIdx.x * blockDim.x + threadIdx.x;
    int tid = threadIdx.x;

    __shared__ float4 s_sw[KC];
    __shared__ float s_aff[6];

    for (int k = tid; k < KC; k += blockDim.x) {
        float4 t;
        t.x = g_src[(n * KC + k) * 2 + 0];
        t.y = g_src[(n * KC + k) * 2 + 1];
        t.z = g_sol[(n * MM + k) * 2 + 0] * HALF_LN2;   // fold 0.5*ln2 for log2f
        t.w = g_sol[(n * MM + k) * 2 + 1] * HALF_LN2;
        s_sw[k] = t;
    }
    if (tid < 6) s_aff[tid] = g_sol[(n * MM + 400) * 2 + tid];
    __syncthreads();

    const float* Wp = g_warp + n * 5 * HW;
    float q0x = Wp[p];
    float q0y = Wp[HW + p];
    float dlx = Wp[2 * HW + p];
    float dly = Wp[3 * HW + p];
    float mk  = Wp[4 * HW + p];
    float q1x = q0x + STEPC;
    float q2y = q0y + STEPC;

    float a0x = 0.f, a0y = 0.f, a1x = 0.f, a1y = 0.f, a2x = 0.f, a2y = 0.f;

    #pragma unroll 4
    for (int k = 0; k < KC; ++k) {
        float4 s = s_sw[k];
        float d0x = q0x - s.x;
        float d0y = q0y - s.y;
        float d1x = q1x - s.x;
        float d2y = q2y - s.y;
        float r0 = d0x * d0x + d0y * d0y;
        float r1 = d1x * d1x + d0y * d0y;
        float r2 = d0x * d0x + d2y * d2y;
        float u0 = r0 * __log2f(r0 + EPSV);
        float u1 = r1 * __log2f(r1 + EPSV);
        float u2 = r2 * __log2f(r2 + EPSV);
        a0x = fmaf(u0, s.z, a0x);  a0y = fmaf(u0, s.w, a0y);
        a1x = fmaf(u1, s.z, a1x);  a1y = fmaf(u1, s.w, a1y);
        a2x = fmaf(u2, s.z, a2x);  a2y = fmaf(u2, s.w, a2y);
    }

    float c0x = a0x + s_aff[0] + s_aff[2] * q0x + s_aff[4] * q0y;
    float c0y = a0y + s_aff[1] + s_aff[3] * q0x + s_aff[5] * q0y;
    float c1x = a1x + s_aff[0] + s_aff[2] * q1x + s_aff[4] * q0y;
    float c1y = a1y + s_aff[1] + s_aff[3] * q1x + s_aff[5] * q0y;
    float c2x = a2x + s_aff[0] + s_aff[2] * q0x + s_aff[4] * q2y;
    float c2y = a2y + s_aff[1] + s_aff[3] * q0x + s_aff[5] * q2y;

    float ja = (c1x - c0x) / STEPC;
    float jb = (c1y - c0y) / STEPC;
    float jc = (c2x - c0x) / STEPC;
    float jd = (c2y - c0y) / STEPC;

    float dnx = ja * dlx + jc * dly;
    float dny = jb * dlx + jd * dly;

    int i = p / WW;
    int j = p - i * WW;
    float gx = j * STEPC - 1.0f;
    float gy = i * STEPC - 1.0f;
    float dfx = (gx + dnx) * mk - 2.0f * (1.0f - mk);
    float dfy = (gy + dny) * mk - 2.0f * (1.0f - mk);

    outDef[(n * HW + p) * 2 + 0] = dfx;
    outDef[(n * HW + p) * 2 + 1] = dfy;
}

// ---------------- launch ----------------
extern "C" void kernel_launch(void* const* d_in, const int* in_sizes, int n_in,
                              void* d_out, int out_size)
{
    const float* a0 = (const float*)d_in[0];
    const float* a1 = (const float*)d_in[1];
    const float* duv;
    const float* uv;
    if (in_sizes[0] == 2 * HW) { duv = a0; uv = a1; }
    else                        { duv = a1; uv = a0; }

    float* out = (float*)d_out;
    float* outDef  = out;
    float* outMask = out + NBATCH * HW * 2;

    static int attr_done = 0;
    if (!attr_done) {
        cudaFuncSetAttribute(panel_kernel,
                             cudaFuncAttributeMaxDynamicSharedMemorySize,
                             MM * 65 * (int)sizeof(float));
        cudaFuncSetAttribute(fused_update,
                             cudaFuncAttributeMaxDynamicSharedMemorySize,
                             (128 + 64 + 64) * 65 * (int)sizeof(float));
        attr_done = 1;
    }

    warp_kernel<<<(NBATCH * HW + 255) / 256, 256>>>(duv, uv, outMask);
    build_kernel<<<dim3(NBATCH, 8), 256>>>();

    for (int k0 = 0; k0 < MM; k0 += NB) {
        int nb = (MM - k0 < NB) ? (MM - k0) : NB;
        int R = MM - k0;
        panel_kernel<<<NBATCH, 1024, R * 65 * sizeof(float)>>>(k0, nb);
        int c2 = NCOL - (k0 + nb);
        if (c2 > 0) {
            int nslabs = (c2 + 63) / 64;
            fused_update<<<dim3(nslabs, NBATCH), 256,
                           (128 + 64 + 64) * 65 * sizeof(float)>>>(k0, nb);
        }
    }

    backsub_kernel<<<NBATCH, 256>>>();
    eval_kernel<<<dim3(HW / 256, NBATCH), 256>>>(outDef);
}

// round 5
// speedup vs baseline: 1.0127x; 1.0127x over previous
#include <cuda_runtime.h>
#include <math.h>

#define HH 192
#define WW 192
#define HW (HH*WW)
#define NBATCH 6
#define KC 400
#define MM 403
#define NCOL 405
#define SRIDE 416
#define NB 64
#define LAMBDAV 100.0f
#define BIGV 1.0e8f
#define EPSV 1.0e-9f
#define STEPC (2.0f/191.0f)
#define HALF_LN2 0.34657359028f
#define NCTAS 144
#define NTH 512

// ---------------- device scratch ----------------
__device__ float g_A[NBATCH * MM * SRIDE];
__device__ float g_warp[NBATCH * 5 * HW];
__device__ float g_src[NBATCH * KC * 2];
__device__ float g_ctrl[NBATCH * 5 * KC];    // sx, sy, m, dx, dy
__device__ float g_sol[NBATCH * MM * 2];
__device__ int   g_swaplist[NBATCH * 128];
__device__ int   g_swapcount[NBATCH];
__device__ unsigned          g_barcnt;       // zero-init; returns to 0 after each barrier
__device__ volatile unsigned g_bargen;

// ---------------- device-wide software barrier ----------------
__device__ __forceinline__ void gbar()
{
    __syncthreads();
    if (threadIdx.x == 0) {
        unsigned gen = g_bargen;
        __threadfence();
        if (atomicAdd(&g_barcnt, 1u) == NCTAS - 1) {
            atomicExch(&g_barcnt, 0u);
            __threadfence();
            g_bargen = gen + 1;
        } else {
            while (g_bargen == gen) { __nanosleep(64); }
        }
        __threadfence();
    }
    __syncthreads();
}

// ---------------- Stage 1: backward warp ----------------
__global__ void warp_kernel(const float* __restrict__ duv,
                            const float* __restrict__ uv,
                            float* __restrict__ outMask)
{
    int idx = blockIdx.x * blockDim.x + threadIdx.x;
    if (idx >= NBATCH * HW) return;
    int n = idx / HW;
    int p = idx - n * HW;

    float u = uv[idx * 2 + 0];
    float v = uv[idx * 2 + 1];
    float x = (u + 1.0f) * 0.5f * (float)(WW - 1);
    float y = (v + 1.0f) * 0.5f * (float)(HH - 1);
    float x0f = floorf(x), y0f = floorf(y);
    float wx = x - x0f, wy = y - y0f;
    int x0 = (int)x0f, y0 = (int)y0f;

    float w00 = (1.0f - wx) * (1.0f - wy);
    float w10 = wx * (1.0f - wy);
    float w01 = (1.0f - wx) * wy;
    float w11 = wx * wy;

    float acc0 = 0.f, acc1 = 0.f, acc2 = 0.f, acc3 = 0.f, acc4 = 0.f;

    const int dxs[4] = {0, 1, 0, 1};
    const int dys[4] = {0, 0, 1, 1};
    const float wts[4] = {w00, w10, w01, w11};

    #pragma unroll
    for (int c = 0; c < 4; ++c) {
        int xi = x0 + dxs[c];
        int yi = y0 + dys[c];
        if (xi >= 0 && xi < WW && yi >= 0 && yi < HH) {
            int q = yi * WW + xi;
            float dux = duv[q * 2 + 0];
            float duy = duv[q * 2 + 1];
            float val = (fabsf(dux) <= 1.0f && fabsf(duy) <= 1.0f) ? 1.0f : 0.0f;
            float gx = xi * STEPC - 1.0f;
            float gy = yi * STEPC - 1.0f;
            float w = wts[c];
            acc0 += gx * w;
            acc1 += gy * w;
            acc2 += (dux - gx) * val * w;
            acc3 += (duy - gy) * val * w;
            acc4 += val * w;
        }
    }

    float mk = (acc4 > 0.5f) ? 1.0f : 0.0f;
    float* Wp = g_warp + n * 5 * HW;
    Wp[0 * HW + p] = acc0;
    Wp[1 * HW + p] = acc1;
    Wp[2 * HW + p] = acc2;
    Wp[3 * HW + p] = acc3;
    Wp[4 * HW + p] = mk;
    outMask[idx] = mk;
}

// ---------------- persistent solver: build + LU + backsub in ONE launch ----------------
__global__ void __launch_bounds__(NTH, 1) solve_kernel()
{
    extern __shared__ float sm[];
    int cta  = blockIdx.x;
    int tid  = threadIdx.x;
    int lane = tid & 31;
    int wid  = tid >> 5;

    __shared__ int s_pvt[64];
    __shared__ int s_perm[448];

    // ===== Phase 0a: control-point data (6 CTAs) =====
    if (cta < NBATCH) {
        int n = cta;
        const float* Wp = g_warp + n * 5 * HW;
        for (int k = tid; k < KC; k += NTH) {
            int a = k / 20, b = k - a * 20;
            int ii = __double2int_rn(a * (191.0 / 19.0));
            int jj = __double2int_rn(b * (191.0 / 19.0));
            int p = ii * WW + jj;
            float sx = Wp[p];
            float sy = Wp[HW + p];
            float m  = Wp[4 * HW + p];
            g_ctrl[(n * 5 + 0) * KC + k] = sx;
            g_ctrl[(n * 5 + 1) * KC + k] = sy;
            g_ctrl[(n * 5 + 2) * KC + k] = m;
            g_ctrl[(n * 5 + 3) * KC + k] = jj * STEPC - 1.0f;
            g_ctrl[(n * 5 + 4) * KC + k] = ii * STEPC - 1.0f;
            g_src[(n * KC + k) * 2 + 0] = sx;
            g_src[(n * KC + k) * 2 + 1] = sy;
        }
    }
    gbar();

    // ===== Phase 0b: build matrix rows (all CTAs; 24 CTAs per matrix) =====
    {
        int n   = cta % NBATCH;
        int blk = cta / NBATCH;          // 0..23
        float* s_sx = sm;
        float* s_sy = sm + KC;
        float* s_m  = sm + 2 * KC;
        float* s_dx = sm + 3 * KC;
        float* s_dy = sm + 4 * KC;
        for (int k = tid; k < KC; k += NTH) {
            s_sx[k] = g_ctrl[(n * 5 + 0) * KC + k];
            s_sy[k] = g_ctrl[(n * 5 + 1) * KC + k];
            s_m[k]  = g_ctrl[(n * 5 + 2) * KC + k];
            s_dx[k] = g_ctrl[(n * 5 + 3) * KC + k];
            s_dy[k] = g_ctrl[(n * 5 + 4) * KC + k];
        }
        __syncthreads();
        float* A = g_A + n * MM * SRIDE;
        int r0 = blk * 17;
        int r1 = min(MM, r0 + 17);
        for (int i = r0; i < r1; ++i) {
            for (int j = tid; j < NCOL; j += NTH) {
                float vout;
                if (i < KC) {
                    if (j < KC) {
                        float dx = s_sx[i] - s_sx[j];
                        float dy = s_sy[i] - s_sy[j];
                        float r2 = dx * dx + dy * dy;
                        vout = 0.5f * r2 * __logf(r2 + EPSV);
                        if (i == j) vout += LAMBDAV + BIGV * (1.0f - s_m[i]);
                    } else if (j == 400) vout = 1.0f;
                    else if (j == 401) vout = s_sx[i];
                    else if (j == 402) vout = s_sy[i];
                    else if (j == 403) vout = s_dx[i];
                    else               vout = s_dy[i];
                } else {
                    if (j < KC) {
                        vout = (i == 400) ? 1.0f : ((i == 401) ? s_sx[j] : s_sy[j]);
                    } else {
                        vout = 0.0f;
                    }
                }
                A[i * SRIDE + j] = vout;
            }
        }
    }
    gbar();

    // ===== LU panel loop =====
    for (int k0 = 0; k0 < MM; k0 += NB) {
        int nb = (MM - k0 < NB) ? (MM - k0) : NB;
        int R  = MM - k0;

        // ---- Phase P: panel factorization (CTAs 0..5, smem-resident) ----
        if (cta < NBATCH) {
            int n = cta;
            float* A = g_A + n * MM * SRIDE;
            float* sP = sm;                      // R x 65

            for (int idx = tid; idx < R * nb; idx += NTH) {
                int r = idx / nb, c = idx - r * nb;
                sP[r * 65 + c] = A[(k0 + r) * SRIDE + k0 + c];
            }
            for (int r = tid; r < R; r += NTH) s_perm[r] = r;
            __syncthreads();

            for (int j = 0; j < nb; ++j) {
                if (wid == 0) {
                    float best = -1.0f; int brow = j;
                    for (int r = j + lane; r < R; r += 32) {
                        float v = fabsf(sP[r * 65 + j]);
                        if (v > best) { best = v; brow = r; }
                    }
                    #pragma unroll
                    for (int off = 16; off > 0; off >>= 1) {
                        float ov = __shfl_down_sync(0xffffffffu, best, off);
                        int   orow = __shfl_down_sync(0xffffffffu, brow, off);
                        if (ov > best) { best = ov; brow = orow; }
                    }
                    brow = __shfl_sync(0xffffffffu, brow, 0);
                    if (brow != j) {
                        for (int c = lane; c < nb; c += 32) {
                            float t = sP[j * 65 + c];
                            sP[j * 65 + c] = sP[brow * 65 + c];
                            sP[brow * 65 + c] = t;
                        }
                    }
                    if (lane == 0) s_pvt[j] = brow;
                }
                __syncthreads();

                float pivinv = 1.0f / sP[j * 65 + j];
                for (int r = j + 1 + wid; r < R; r += 16) {
                    float m = sP[r * 65 + j] * pivinv;
                    for (int c = j + 1 + lane; c < nb; c += 32)
                        sP[r * 65 + c] = fmaf(-m, sP[j * 65 + c], sP[r * 65 + c]);
                    if (lane == 0) sP[r * 65 + j] = m;
                }
                __syncthreads();
            }

            if (tid == 0) {
                for (int j = 0; j < nb; ++j) {
                    int pj = s_pvt[j];
                    int t = s_perm[j]; s_perm[j] = s_perm[pj]; s_perm[pj] = t;
                }
                int m = 0;
                for (int r = 0; r < R; ++r) {
                    if (s_perm[r] != r) {
                        g_swaplist[n * 128 + m] = (k0 + r) | ((k0 + s_perm[r]) << 16);
                        ++m;
                    }
                }
                g_swapcount[n] = m;
            }
            for (int idx = tid; idx < R * nb; idx += NTH) {
                int r = idx / nb, c = idx - r * nb;
                A[(k0 + r) * SRIDE + k0 + c] = sP[r * 65 + c];
            }
        }
        gbar();

        // ---- Phase U1: swap + trisolve per (matrix, slab) ----
        int c2 = NCOL - (k0 + nb);
        int ns = (c2 > 0) ? (c2 + 63) / 64 : 0;
        for (int t = cta; t < NBATCH * ns; t += NCTAS) {
            int n = t / ns;
            int s = t - n * ns;
            int col0 = k0 + nb + s * 64;
            float* A = g_A + n * MM * SRIDE;

            float* sw = sm;                 // 128 x 65
            float* sL = sm + 128 * 65;      // 64 x 65
            float* sB = sL + 64 * 65;       // 64 x 65

            int tx = tid & 63;
            int ty = tid >> 6;              // 8 groups
            int c = col0 + tx;

            int m = g_swapcount[n];
            for (int si = ty; si < m; si += 8) {
                int pack = g_swaplist[n * 128 + si];
                int src = pack >> 16;
                if (c < NCOL) sw[si * 65 + tx] = A[src * SRIDE + c];
            }
            __syncthreads();
            for (int si = ty; si < m; si += 8) {
                int pack = g_swaplist[n * 128 + si];
                int dest = pack & 0xFFFF;
                if (c < NCOL) A[dest * SRIDE + c] = sw[si * 65 + tx];
            }
            __syncthreads();

            for (int idx = tid; idx < nb * nb; idx += NTH) {
                int r = idx / nb, cc = idx - r * nb;
                sL[r * 65 + cc] = A[(k0 + r) * SRIDE + k0 + cc];
            }
            for (int idx = tid; idx < nb * 64; idx += NTH) {
                int r = idx >> 6, cc = idx & 63;
                int gc = col0 + cc;
                sB[r * 65 + cc] = (gc < NCOL) ? A[(k0 + r) * SRIDE + gc] : 0.0f;
            }
            __syncthreads();
            for (int i = 0; i < nb - 1; ++i) {
                float bi = sB[i * 65 + tx];
                for (int jj = i + 1 + ty; jj < nb; jj += 8)
                    sB[jj * 65 + tx] = fmaf(-sL[jj * 65 + i], bi, sB[jj * 65 + tx]);
                __syncthreads();
            }
            for (int idx = tid; idx < nb * 64; idx += NTH) {
                int r = idx >> 6, cc = idx & 63;
                int gc = col0 + cc;
                if (gc < NCOL) A[(k0 + r) * SRIDE + gc] = sB[r * 65 + cc];
            }
            __syncthreads();
        }
        gbar();

        // ---- Phase U2: GEMM tiles A22 -= L21 * U12 ----
        int r2 = MM - (k0 + nb);
        int nr = (r2 > 0) ? (r2 + 63) / 64 : 0;
        int ntasks = NBATCH * ns * nr;
        for (int t = cta; t < ntasks; t += NCTAS) {
            int n   = t / (ns * nr);
            int rem = t - n * (ns * nr);
            int s   = rem / nr;
            int rt  = rem - s * nr;
            int col0 = k0 + nb + s * 64;
            int row0 = k0 + nb + rt * 64;
            float* A = g_A + n * MM * SRIDE;

            float* As = sm;                 // 64 x 65
            float* Bs = sm + 64 * 65;       // 64 x 65

            for (int idx = tid; idx < 64 * 64; idx += NTH) {
                int a = idx >> 6, b = idx & 63;
                int r = row0 + a;
                As[a * 65 + b] = (r < MM && b < nb) ? A[r * SRIDE + k0 + b] : 0.0f;
                int gc = col0 + b;
                Bs[a * 65 + b] = (a < nb && gc < NCOL) ? A[(k0 + a) * SRIDE + gc] : 0.0f;
            }
            __syncthreads();

            int ty2 = (tid >> 4) * 2;       // rows
            int tx4 = (tid & 15) * 4;       // cols

            float acc[2][4];
            #pragma unroll
            for (int i = 0; i < 2; ++i)
                #pragma unroll
                for (int j = 0; j < 4; ++j) acc[i][j] = 0.0f;

            for (int kk = 0; kk < nb; ++kk) {
                float a0 = As[(ty2 + 0) * 65 + kk];
                float a1 = As[(ty2 + 1) * 65 + kk];
                float b0 = Bs[kk * 65 + tx4 + 0];
                float b1 = Bs[kk * 65 + tx4 + 1];
                float b2 = Bs[kk * 65 + tx4 + 2];
                float b3 = Bs[kk * 65 + tx4 + 3];
                acc[0][0] = fmaf(a0, b0, acc[0][0]); acc[0][1] = fmaf(a0, b1, acc[0][1]);
                acc[0][2] = fmaf(a0, b2, acc[0][2]); acc[0][3] = fmaf(a0, b3, acc[0][3]);
                acc[1][0] = fmaf(a1, b0, acc[1][0]); acc[1][1] = fmaf(a1, b1, acc[1][1]);
                acc[1][2] = fmaf(a1, b2, acc[1][2]); acc[1][3] = fmaf(a1, b3, acc[1][3]);
            }

            #pragma unroll
            for (int i = 0; i < 2; ++i) {
                int r = row0 + ty2 + i;
                if (r >= MM) continue;
                #pragma unroll
                for (int j = 0; j < 4; ++j) {
                    int gc = col0 + tx4 + j;
                    if (gc < NCOL) A[r * SRIDE + gc] -= acc[i][j];
                }
            }
            __syncthreads();
        }
        gbar();
    }

    // ===== back-substitution (CTAs 0..5) =====
    if (cta < NBATCH) {
        int n = cta;
        float* A = g_A + n * MM * SRIDE;
        float* sD  = sm;                 // 64 x 65
        float* x0s = sm + 64 * 65;       // MM
        float* x1s = x0s + MM;

        for (int j = tid; j < MM; j += NTH) {
            x0s[j] = A[j * SRIDE + 403];
            x1s[j] = A[j * SRIDE + 404];
        }
        __syncthreads();

        for (int b = 6; b >= 0; --b) {
            int bk0 = b * 64;
            int bnb = (MM - bk0 < 64) ? (MM - bk0) : 64;

            for (int idx = tid; idx < bnb * bnb; idx += NTH) {
                int r = idx / bnb, cc = idx - r * bnb;
                sD[r * 65 + cc] = A[(bk0 + r) * SRIDE + bk0 + cc];
            }
            __syncthreads();

            if (wid == 0) {
                for (int k = bnb - 1; k >= 0; --k) {
                    float s0 = 0.f, s1 = 0.f;
                    for (int j = k + 1 + lane; j < bnb; j += 32) {
                        float u = sD[k * 65 + j];
                        s0 = fmaf(u, x0s[bk0 + j], s0);
                        s1 = fmaf(u, x1s[bk0 + j], s1);
                    }
                    #pragma unroll
                    for (int off = 16; off > 0; off >>= 1) {
                        s0 += __shfl_down_sync(0xffffffffu, s0, off);
                        s1 += __shfl_down_sync(0xffffffffu, s1, off);
                    }
                    if (lane == 0) {
                        float d = 1.0f / sD[k * 65 + k];
                        x0s[bk0 + k] = (x0s[bk0 + k] - s0) * d;
                        x1s[bk0 + k] = (x1s[bk0 + k] - s1) * d;
                    }
                    __syncwarp();
                }
            }
            __syncthreads();

            for (int r = tid; r < bk0; r += NTH) {
                float s0 = 0.f, s1 = 0.f;
                const float* Ur = A + r * SRIDE + bk0;
                #pragma unroll 8
                for (int j = 0; j < bnb; ++j) {
                    float u = Ur[j];
                    s0 = fmaf(u, x0s[bk0 + j], s0);
                    s1 = fmaf(u, x1s[bk0 + j], s1);
                }
                x0s[r] -= s0;
                x1s[r] -= s1;
            }
            __syncthreads();
        }

        for (int j = tid; j < MM; j += NTH) {
            g_sol[(n * MM + j) * 2 + 0] = x0s[j];
            g_sol[(n * MM + j) * 2 + 1] = x1s[j];
        }
    }
}

// ---------------- Stage 4: TPS evaluation + Jacobian + output ----------------
__global__ void __launch_bounds__(256) eval_kernel(float* __restrict__ outDef)
{
    int n = blockIdx.y;
    int p = blockIdx.x * blockDim.x + threadIdx.x;
    int tid = threadIdx.x;

    __shared__ float4 s_sw[KC];
    __shared__ float s_aff[6];

    for (int k = tid; k < KC; k += blockDim.x) {
        float4 t;
        t.x = g_src[(n * KC + k) * 2 + 0];
        t.y = g_src[(n * KC + k) * 2 + 1];
        t.z = g_sol[(n * MM + k) * 2 + 0] * HALF_LN2;
        t.w = g_sol[(n * MM + k) * 2 + 1] * HALF_LN2;
        s_sw[k] = t;
    }
    if (tid < 6) s_aff[tid] = g_sol[(n * MM + 400) * 2 + tid];
    __syncthreads();

    const float* Wp = g_warp + n * 5 * HW;
    float q0x = Wp[p];
    float q0y = Wp[HW + p];
    float dlx = Wp[2 * HW + p];
    float dly = Wp[3 * HW + p];
    float mk  = Wp[4 * HW + p];
    float q1x = q0x + STEPC;
    float q2y = q0y + STEPC;

    float a0x = 0.f, a0y = 0.f, a1x = 0.f, a1y = 0.f, a2x = 0.f, a2y = 0.f;

    #pragma unroll 4
    for (int k = 0; k < KC; ++k) {
        float4 s = s_sw[k];
        float d0x = q0x - s.x;
        float d0y = q0y - s.y;
        float d1x = q1x - s.x;
        float d2y = q2y - s.y;
        float r0 = d0x * d0x + d0y * d0y;
        float r1 = d1x * d1x + d0y * d0y;
        float r2 = d0x * d0x + d2y * d2y;
        float u0 = r0 * __log2f(r0 + EPSV);
        float u1 = r1 * __log2f(r1 + EPSV);
        float u2 = r2 * __log2f(r2 + EPSV);
        a0x = fmaf(u0, s.z, a0x);  a0y = fmaf(u0, s.w, a0y);
        a1x = fmaf(u1, s.z, a1x);  a1y = fmaf(u1, s.w, a1y);
        a2x = fmaf(u2, s.z, a2x);  a2y = fmaf(u2, s.w, a2y);
    }

    float c0x = a0x + s_aff[0] + s_aff[2] * q0x + s_aff[4] * q0y;
    float c0y = a0y + s_aff[1] + s_aff[3] * q0x + s_aff[5] * q0y;
    float c1x = a1x + s_aff[0] + s_aff[2] * q1x + s_aff[4] * q0y;
    float c1y = a1y + s_aff[1] + s_aff[3] * q1x + s_aff[5] * q0y;
    float c2x = a2x + s_aff[0] + s_aff[2] * q0x + s_aff[4] * q2y;
    float c2y = a2y + s_aff[1] + s_aff[3] * q0x + s_aff[5] * q2y;

    float ja = (c1x - c0x) / STEPC;
    float jb = (c1y - c0y) / STEPC;
    float jc = (c2x - c0x) / STEPC;
    float jd = (c2y - c0y) / STEPC;

    float dnx = ja * dlx + jc * dly;
    float dny = jb * dlx + jd * dly;

    int i = p / WW;
    int j = p - i * WW;
    float gx = j * STEPC - 1.0f;
    float gy = i * STEPC - 1.0f;
    float dfx = (gx + dnx) * mk - 2.0f * (1.0f - mk);
    float dfy = (gy + dny) * mk - 2.0f * (1.0f - mk);

    outDef[(n * HW + p) * 2 + 0] = dfx;
    outDef[(n * HW + p) * 2 + 1] = dfy;
}

// ---------------- launch ----------------
extern "C" void kernel_launch(void* const* d_in, const int* in_sizes, int n_in,
                              void* d_out, int out_size)
{
    const float* a0 = (const float*)d_in[0];
    const float* a1 = (const float*)d_in[1];
    const float* duv;
    const float* uv;
    if (in_sizes[0] == 2 * HW) { duv = a0; uv = a1; }
    else                        { duv = a1; uv = a0; }

    float* out = (float*)d_out;
    float* outDef  = out;
    float* outMask = out + NBATCH * HW * 2;

    // dynamic smem: 403*65 floats covers every phase's carve-out
    const int SMBYTES = MM * 65 * (int)sizeof(float);
    cudaFuncSetAttribute(solve_kernel,
                         cudaFuncAttributeMaxDynamicSharedMemorySize, SMBYTES);

    warp_kernel<<<(NBATCH * HW + 255) / 256, 256>>>(duv, uv, outMask);
    solve_kernel<<<NCTAS, NTH, SMBYTES>>>();
    eval_kernel<<<dim3(HW / 256, NBATCH), 256>>>(outDef);
}

// round 6
// speedup vs baseline: 1.4519x; 1.4336x over previous
#include <cuda_runtime.h>
#include <math.h>

#define HH 192
#define WW 192
#define HW (HH*WW)
#define NBATCH 6
#define KC 400
#define MM 403
#define NCOL 405
#define SRIDE 416
#define LAMBDAV 100.0f
#define BIGV 1.0e8f
#define EPSV 1.0e-9f
#define STEPC (2.0f/191.0f)
#define HALF_LN2 0.34657359028f
#define NTH 512
#define NPAN 7                 // ceil(403/64)

// ---------------- device scratch ----------------
__device__ float g_A[NBATCH * MM * SRIDE];
__device__ float g_warp[NBATCH * 5 * HW];
__device__ float g_src[NBATCH * KC * 2];
__device__ float g_sol[NBATCH * MM * 2];
__device__ unsigned g_buildcnt[NBATCH];
__device__ unsigned g_panelflag[NBATCH];
__device__ unsigned g_prog[NBATCH * 8];

__device__ __forceinline__ unsigned ldv(unsigned* p) { return *(volatile unsigned*)p; }

// ---------------- Stage 1: backward warp (+ flag reset) ----------------
__global__ void warp_kernel(const float* __restrict__ duv,
                            const float* __restrict__ uv,
                            float* __restrict__ outMask)
{
    if (blockIdx.x == 0) {
        if (threadIdx.x < NBATCH) {
            g_buildcnt[threadIdx.x] = 0;
            g_panelflag[threadIdx.x] = 0;
        }
        if (threadIdx.x < NBATCH * 8) g_prog[threadIdx.x] = 0;
    }

    int idx = blockIdx.x * blockDim.x + threadIdx.x;
    if (idx >= NBATCH * HW) return;
    int n = idx / HW;
    int p = idx - n * HW;

    float u = uv[idx * 2 + 0];
    float v = uv[idx * 2 + 1];
    float x = (u + 1.0f) * 0.5f * (float)(WW - 1);
    float y = (v + 1.0f) * 0.5f * (float)(HH - 1);
    float x0f = floorf(x), y0f = floorf(y);
    float wx = x - x0f, wy = y - y0f;
    int x0 = (int)x0f, y0 = (int)y0f;

    float w00 = (1.0f - wx) * (1.0f - wy);
    float w10 = wx * (1.0f - wy);
    float w01 = (1.0f - wx) * wy;
    float w11 = wx * wy;

    float acc0 = 0.f, acc1 = 0.f, acc2 = 0.f, acc3 = 0.f, acc4 = 0.f;

    const int dxs[4] = {0, 1, 0, 1};
    const int dys[4] = {0, 0, 1, 1};
    const float wts[4] = {w00, w10, w01, w11};

    #pragma unroll
    for (int c = 0; c < 4; ++c) {
        int xi = x0 + dxs[c];
        int yi = y0 + dys[c];
        if (xi >= 0 && xi < WW && yi >= 0 && yi < HH) {
            int q = yi * WW + xi;
            float dux = duv[q * 2 + 0];
            float duy = duv[q * 2 + 1];
            float val = (fabsf(dux) <= 1.0f && fabsf(duy) <= 1.0f) ? 1.0f : 0.0f;
            float gx = xi * STEPC - 1.0f;
            float gy = yi * STEPC - 1.0f;
            float w = wts[c];
            acc0 += gx * w;
            acc1 += gy * w;
            acc2 += (dux - gx) * val * w;
            acc3 += (duy - gy) * val * w;
            acc4 += val * w;
        }
    }

    float mk = (acc4 > 0.5f) ? 1.0f : 0.0f;
    float* Wp = g_warp + n * 5 * HW;
    Wp[0 * HW + p] = acc0;
    Wp[1 * HW + p] = acc1;
    Wp[2 * HW + p] = acc2;
    Wp[3 * HW + p] = acc3;
    Wp[4 * HW + p] = mk;
    outMask[idx] = mk;
}

// shared scratch: 10240 floats = 40 KB (build ctrl / sL+Bs+As / backsub)
__shared__ float smbuf[10240];
__shared__ float s_piv[2][64];
__shared__ float s_pvi[2];

// ---------------- slab update: trisolve block B wrt panel j, then GEMM ----------------
__device__ __noinline__ void slab_update(float* A, int j, int B, int tid)
{
    float* sL = smbuf;              // 64x64 L11
    float* Bs = smbuf + 4096;       // 64x64 U12 slab
    float* As = smbuf + 8192;       // 32x64 L21 tile

    int k0 = 64 * j;
    int col0 = 64 * B;
    int w = NCOL - col0; if (w > 64) w = 64;

    for (int idx = tid; idx < 4096; idx += NTH) {
        int r = idx >> 6, c = idx & 63;
        sL[idx] = A[(k0 + r) * SRIDE + k0 + c];
    }
    __syncthreads();

    if (tid < w) {
        float x[64];
        const float* colp = A + k0 * SRIDE + col0 + tid;
        #pragma unroll
        for (int r = 0; r < 64; ++r) x[r] = colp[r * SRIDE];
        #pragma unroll
        for (int i = 0; i < 64; ++i) {
            float xi = x[i];
            #pragma unroll
            for (int jj = i + 1; jj < 64; ++jj)
                x[jj] = fmaf(-sL[jj * 64 + i], xi, x[jj]);
        }
        float* outc = A + k0 * SRIDE + col0 + tid;
        #pragma unroll
        for (int r = 0; r < 64; ++r) {
            Bs[r * 64 + tid] = x[r];
            outc[r * SRIDE] = x[r];
        }
    }
    __syncthreads();

    // GEMM: rows k0+64 .. MM-1, tiles of 32 rows
    int c = tid & 63;
    int rg4 = (tid >> 6) * 4;
    for (int row0 = k0 + 64; row0 < MM; row0 += 32) {
        for (int idx = tid; idx < 2048; idx += NTH) {
            int r = idx >> 6, cc = idx & 63;
            int gr = row0 + r;
            As[idx] = (gr < MM) ? A[gr * SRIDE + k0 + cc] : 0.0f;
        }
        __syncthreads();

        float a0 = 0.f, a1 = 0.f, a2 = 0.f, a3 = 0.f;
        #pragma unroll
        for (int kk = 0; kk < 64; ++kk) {
            float b = Bs[kk * 64 + c];
            a0 = fmaf(As[(rg4 + 0) * 64 + kk], b, a0);
            a1 = fmaf(As[(rg4 + 1) * 64 + kk], b, a1);
            a2 = fmaf(As[(rg4 + 2) * 64 + kk], b, a2);
            a3 = fmaf(As[(rg4 + 3) * 64 + kk], b, a3);
        }
        if (c < w) {
            int gr = row0 + rg4;
            if (gr + 0 < MM) A[(gr + 0) * SRIDE + col0 + c] -= a0;
            if (gr + 1 < MM) A[(gr + 1) * SRIDE + col0 + c] -= a1;
            if (gr + 2 < MM) A[(gr + 2) * SRIDE + col0 + c] -= a2;
            if (gr + 3 < MM) A[(gr + 3) * SRIDE + col0 + c] -= a3;
        }
        __syncthreads();
    }
}

// ---------------- solver: build + dataflow LU + backsub ----------------
__global__ void __launch_bounds__(NTH, 1) solve_kernel()
{
    int cta = blockIdx.x;
    int tid = threadIdx.x;
    int lane = tid & 31;
    int wid = tid >> 5;

    // ===== build phase: 144 CTAs, 24 per matrix =====
    {
        int n = cta % NBATCH;
        int part = cta / NBATCH;            // 0..23
        float* s_sx = smbuf;
        float* s_sy = smbuf + KC;
        float* s_m  = smbuf + 2 * KC;
        float* s_dx = smbuf + 3 * KC;
        float* s_dy = smbuf + 4 * KC;

        const float* Wp = g_warp + n * 5 * HW;
        for (int k = tid; k < KC; k += NTH) {
            int a = k / 20, b = k - a * 20;
            int ii = __double2int_rn(a * (191.0 / 19.0));
            int jj = __double2int_rn(b * (191.0 / 19.0));
            int p = ii * WW + jj;
            float sx = Wp[p];
            float sy = Wp[HW + p];
            float m  = Wp[4 * HW + p];
            s_sx[k] = sx; s_sy[k] = sy; s_m[k] = m;
            s_dx[k] = jj * STEPC - 1.0f;
            s_dy[k] = ii * STEPC - 1.0f;
            if (part == 0) {
                g_src[(n * KC + k) * 2 + 0] = sx;
                g_src[(n * KC + k) * 2 + 1] = sy;
            }
        }
        __syncthreads();

        float* A = g_A + n * MM * SRIDE;
        int r0 = part * 17;
        int r1 = min(MM, r0 + 17);
        for (int i = r0; i < r1; ++i) {
            for (int j = tid; j < NCOL; j += NTH) {
                float vout;
                if (i < KC) {
                    if (j < KC) {
                        float dx = s_sx[i] - s_sx[j];
                        float dy = s_sy[i] - s_sy[j];
                        float r2 = dx * dx + dy * dy;
                        vout = 0.5f * r2 * __logf(r2 + EPSV);
                        if (i == j) vout += LAMBDAV + BIGV * (1.0f - s_m[i]);
                    } else if (j == 400) vout = 1.0f;
                    else if (j == 401) vout = s_sx[i];
                    else if (j == 402) vout = s_sy[i];
                    else if (j == 403) vout = s_dx[i];
                    else               vout = s_dy[i];
                } else {
                    if (j < KC) {
                        vout = (i == 400) ? 1.0f : ((i == 401) ? s_sx[j] : s_sy[j]);
                    } else {
                        vout = 0.0f;
                    }
                }
                A[i * SRIDE + j] = vout;
            }
        }
        __threadfence();
        __syncthreads();
        if (tid == 0) atomicAdd(&g_buildcnt[n], 1u);
    }
    if (cta >= 36) return;
    __syncthreads();

    // ===== slab CTAs: cta 6..35 =====
    if (cta >= NBATCH) {
        int idx = cta - NBATCH;
        int n = idx / 5;
        int B = 2 + idx % 5;                 // blocks 2..6
        float* A = g_A + n * MM * SRIDE;
        for (int j = 0; j <= B - 2; ++j) {
            if (tid == 0) { while (ldv(&g_panelflag[n]) < (unsigned)(j + 1)) __nanosleep(64); }
            __syncthreads();
            __threadfence();
            slab_update(A, j, B, tid);
            __threadfence();
            __syncthreads();
            if (tid == 0) atomicExch(&g_prog[n * 8 + B], (unsigned)(j + 1));
        }
        return;
    }

    // ===== panel CTA: cta = n in 0..5 =====
    int n = cta;
    float* A = g_A + n * MM * SRIDE;

    if (tid == 0) { while (ldv(&g_buildcnt[n]) < 24u) __nanosleep(64); }
    __syncthreads();
    __threadfence();

    for (int k = 0; k < NPAN; ++k) {
        int k0 = 64 * k;
        int nb = MM - k0; if (nb > 64) nb = 64;
        int R  = MM - k0;
        bool active = (tid < R);

        // --- register-resident panel factorization (no pivoting) ---
        float rgv[64];
        {
            const float* rowp = A + (k0 + tid) * SRIDE + k0;
            if (active) {
                if (nb == 64) {
                    #pragma unroll
                    for (int c4 = 0; c4 < 64; c4 += 4) {
                        float4 v = *(const float4*)&rowp[c4];
                        rgv[c4 + 0] = v.x; rgv[c4 + 1] = v.y;
                        rgv[c4 + 2] = v.z; rgv[c4 + 3] = v.w;
                    }
                } else {
                    #pragma unroll
                    for (int c = 0; c < 64; ++c) rgv[c] = (c < nb) ? rowp[c] : 0.0f;
                }
            }
        }
        float nextm = rgv[0];

        for (int j = 0; j < nb; ++j) {
            int jb = j & 1;
            if (tid == j) {
                #pragma unroll
                for (int c = 0; c < 64; ++c) s_piv[jb][c] = rgv[c];
                s_pvi[jb] = 1.0f / nextm;
            }
            __syncthreads();
            if (active && tid > j) {
                float m = nextm * s_pvi[jb];
                float nm2 = 0.0f;
                #pragma unroll
                for (int c = 0; c < 64; ++c) {
                    if (c > j) {
                        rgv[c] = fmaf(-m, s_piv[jb][c], rgv[c]);
                        if (c == j + 1) nm2 = rgv[c];
                    } else if (c == j) {
                        rgv[c] = m;
                    }
                }
                nextm = nm2;
            }
        }

        // write back panel
        if (active) {
            float* rowp = A + (k0 + tid) * SRIDE + k0;
            if (nb == 64) {
                #pragma unroll
                for (int c4 = 0; c4 < 64; c4 += 4) {
                    float4 v;
                    v.x = rgv[c4 + 0]; v.y = rgv[c4 + 1];
                    v.z = rgv[c4 + 2]; v.w = rgv[c4 + 3];
                    *(float4*)&rowp[c4] = v;
                }
            } else {
                #pragma unroll
                for (int c = 0; c < 64; ++c) if (c < nb) rowp[c] = rgv[c];
            }
        }
        __threadfence();
        __syncthreads();
        if (tid == 0) atomicExch(&g_panelflag[n], (unsigned)(k + 1));

        if (k < NPAN - 1) {
            int Bb = k + 1;
            if (Bb >= 2) {
                if (tid == 0) { while (ldv(&g_prog[n * 8 + Bb]) < (unsigned)k) __nanosleep(64); }
                __syncthreads();
                __threadfence();
            }
            slab_update(A, k, Bb, tid);
            __syncthreads();
        } else {
            // final: trisolve RHS cols 403,404 (rows 384..402) wrt unit-lower L66
            float* sL = smbuf;
            for (int idx = tid; idx < 19 * 19; idx += NTH) {
                int r = idx / 19, c = idx - r * 19;
                sL[r * 64 + c] = A[(384 + r) * SRIDE + 384 + c];
            }
            __syncthreads();
            if (tid < 2) {
                float x[19];
                float* colp = A + 384 * SRIDE + 403 + tid;
                #pragma unroll
                for (int r = 0; r < 19; ++r) x[r] = colp[r * SRIDE];
                #pragma unroll
                for (int i = 0; i < 19; ++i) {
                    float xi = x[i];
                    #pragma unroll
                    for (int jj = i + 1; jj < 19; ++jj)
                        x[jj] = fmaf(-sL[jj * 64 + i], xi, x[jj]);
                }
                #pragma unroll
                for (int r = 0; r < 19; ++r) colp[r * SRIDE] = x[r];
            }
            __syncthreads();
        }
    }

    // ===== back-substitution =====
    {
        float* sD  = smbuf;              // 64x65
        float* x0s = smbuf + 4160;       // MM
        float* x1s = x0s + MM;

        for (int j = tid; j < MM; j += NTH) {
            x0s[j] = A[j * SRIDE + 403];
            x1s[j] = A[j * SRIDE + 404];
        }
        __syncthreads();

        for (int b = 6; b >= 0; --b) {
            int bk0 = b * 64;
            int bnb = (MM - bk0 < 64) ? (MM - bk0) : 64;

            for (int idx = tid; idx < bnb * bnb; idx += NTH) {
                int r = idx / bnb, cc = idx - r * bnb;
                sD[r * 65 + cc] = A[(bk0 + r) * SRIDE + bk0 + cc];
            }
            __syncthreads();

            if (wid == 0) {
                for (int k = bnb - 1; k >= 0; --k) {
                    float s0 = 0.f, s1 = 0.f;
                    for (int j = k + 1 + lane; j < bnb; j += 32) {
                        float u = sD[k * 65 + j];
                        s0 = fmaf(u, x0s[bk0 + j], s0);
                        s1 = fmaf(u, x1s[bk0 + j], s1);
                    }
                    #pragma unroll
                    for (int off = 16; off > 0; off >>= 1) {
                        s0 += __shfl_down_sync(0xffffffffu, s0, off);
                        s1 += __shfl_down_sync(0xffffffffu, s1, off);
                    }
                    if (lane == 0) {
                        float d = 1.0f / sD[k * 65 + k];
                        x0s[bk0 + k] = (x0s[bk0 + k] - s0) * d;
                        x1s[bk0 + k] = (x1s[bk0 + k] - s1) * d;
                    }
                    __syncwarp();
                }
            }
            __syncthreads();

            for (int r = tid; r < bk0; r += NTH) {
                float s0 = 0.f, s1 = 0.f;
                const float* Ur = A + r * SRIDE + bk0;
                #pragma unroll 8
                for (int j = 0; j < bnb; ++j) {
                    float u = Ur[j];
                    s0 = fmaf(u, x0s[bk0 + j], s0);
                    s1 = fmaf(u, x1s[bk0 + j], s1);
                }
                x0s[r] -= s0;
                x1s[r] -= s1;
            }
            __syncthreads();
        }

        for (int j = tid; j < MM; j += NTH) {
            g_sol[(n * MM + j) * 2 + 0] = x0s[j];
            g_sol[(n * MM + j) * 2 + 1] = x1s[j];
        }
    }
}

// ---------------- Stage 4: TPS evaluation + Jacobian + output ----------------
__global__ void __launch_bounds__(256) eval_kernel(float* __restrict__ outDef)
{
    int n = blockIdx.y;
    int p = blockIdx.x * blockDim.x + threadIdx.x;
    int tid = threadIdx.x;

    __shared__ float4 s_sw[KC];
    __shared__ float s_aff[6];

    for (int k = tid; k < KC; k += blockDim.x) {
        float4 t;
        t.x = g_src[(n * KC + k) * 2 + 0];
        t.y = g_src[(n * KC + k) * 2 + 1];
        t.z = g_sol[(n * MM + k) * 2 + 0] * HALF_LN2;
        t.w = g_sol[(n * MM + k) * 2 + 1] * HALF_LN2;
        s_sw[k] = t;
    }
    if (tid < 6) s_aff[tid] = g_sol[(n * MM + 400) * 2 + tid];
    __syncthreads();

    const float* Wp = g_warp + n * 5 * HW;
    float q0x = Wp[p];
    float q0y = Wp[HW + p];
    float dlx = Wp[2 * HW + p];
    float dly = Wp[3 * HW + p];
    float mk  = Wp[4 * HW + p];
    float q1x = q0x + STEPC;
    float q2y = q0y + STEPC;

    float a0x = 0.f, a0y = 0.f, a1x = 0.f, a1y = 0.f, a2x = 0.f, a2y = 0.f;

    #pragma unroll 4
    for (int k = 0; k < KC; ++k) {
        float4 s = s_sw[k];
        float d0x = q0x - s.x;
        float d0y = q0y - s.y;
        float d1x = q1x - s.x;
        float d2y = q2y - s.y;
        float r0 = d0x * d0x + d0y * d0y;
        float r1 = d1x * d1x + d0y * d0y;
        float r2 = d0x * d0x + d2y * d2y;
        float u0 = r0 * __log2f(r0 + EPSV);
        float u1 = r1 * __log2f(r1 + EPSV);
        float u2 = r2 * __log2f(r2 + EPSV);
        a0x = fmaf(u0, s.z, a0x);  a0y = fmaf(u0, s.w, a0y);
        a1x = fmaf(u1, s.z, a1x);  a1y = fmaf(u1, s.w, a1y);
        a2x = fmaf(u2, s.z, a2x);  a2y = fmaf(u2, s.w, a2y);
    }

    float c0x = a0x + s_aff[0] + s_aff[2] * q0x + s_aff[4] * q0y;
    float c0y = a0y + s_aff[1] + s_aff[3] * q0x + s_aff[5] * q0y;
    float c1x = a1x + s_aff[0] + s_aff[2] * q1x + s_aff[4] * q0y;
    float c1y = a1y + s_aff[1] + s_aff[3] * q1x + s_aff[5] * q0y;
    float c2x = a2x + s_aff[0] + s_aff[2] * q0x + s_aff[4] * q2y;
    float c2y = a2y + s_aff[1] + s_aff[3] * q0x + s_aff[5] * q2y;

    float ja = (c1x - c0x) / STEPC;
    float jb = (c1y - c0y) / STEPC;
    float jc = (c2x - c0x) / STEPC;
    float jd = (c2y - c0y) / STEPC;

    float dnx = ja * dlx + jc * dly;
    float dny = jb * dlx + jd * dly;

    int i = p / WW;
    int j = p - i * WW;
    float gx = j * STEPC - 1.0f;
    float gy = i * STEPC - 1.0f;
    float dfx = (gx + dnx) * mk - 2.0f * (1.0f - mk);
    float dfy = (gy + dny) * mk - 2.0f * (1.0f - mk);

    outDef[(n * HW + p) * 2 + 0] = dfx;
    outDef[(n * HW + p) * 2 + 1] = dfy;
}

// ---------------- launch ----------------
extern "C" void kernel_launch(void* const* d_in, const int* in_sizes, int n_in,
                              void* d_out, int out_size)
{
    const float* a0 = (const float*)d_in[0];
    const float* a1 = (const float*)d_in[1];
    const float* duv;
    const float* uv;
    if (in_sizes[0] == 2 * HW) { duv = a0; uv = a1; }
    else                        { duv = a1; uv = a0; }

    float* out = (float*)d_out;
    float* outDef  = out;
    float* outMask = out + NBATCH * HW * 2;

    warp_kernel<<<(NBATCH * HW + 255) / 256, 256>>>(duv, uv, outMask);
    solve_kernel<<<144, NTH>>>();
    eval_kernel<<<dim3(HW / 256, NBATCH), 256>>>(outDef);
}

// round 7
// speedup vs baseline: 1.6686x; 1.1493x over previous
#include <cuda_runtime.h>
#include <math.h>

#define HH 192
#define WW 192
#define HW (HH*WW)
#define NBATCH 6
#define KC 400
#define MM 403
#define NCOL 405
#define SRIDE 416
#define LAMBDAV 100.0f
#define BIGV 1.0e8f
#define EPSV 1.0e-9f
#define STEPC (2.0f/191.0f)
#define HALF_LN2 0.34657359028f
#define NTH 512
#define NPAN 7

// ---------------- device scratch ----------------
__device__ float g_A[NBATCH * MM * SRIDE];
__device__ float g_warp[NBATCH * 5 * HW];
__device__ float g_src[NBATCH * KC * 2];
__device__ float g_sol[NBATCH * MM * 2];
__device__ unsigned g_buildcnt[NBATCH];
__device__ unsigned g_panelflag[NBATCH];
__device__ unsigned g_prog[NBATCH * 8];    // per (n, block) slab-half completion counter
__device__ unsigned g_prog2[NBATCH];       // partner progress

__device__ __forceinline__ unsigned ldv(unsigned* p) { return *(volatile unsigned*)p; }

// ---------------- Stage 1: backward warp (+ flag reset) ----------------
__global__ void warp_kernel(const float* __restrict__ duv,
                            const float* __restrict__ uv,
                            float* __restrict__ outMask)
{
    if (blockIdx.x == 0) {
        if (threadIdx.x < NBATCH) {
            g_buildcnt[threadIdx.x] = 0;
            g_panelflag[threadIdx.x] = 0;
            g_prog2[threadIdx.x] = 0;
        }
        if (threadIdx.x < NBATCH * 8) g_prog[threadIdx.x] = 0;
    }

    int idx = blockIdx.x * blockDim.x + threadIdx.x;
    if (idx >= NBATCH * HW) return;
    int n = idx / HW;
    int p = idx - n * HW;

    float u = uv[idx * 2 + 0];
    float v = uv[idx * 2 + 1];
    float x = (u + 1.0f) * 0.5f * (float)(WW - 1);
    float y = (v + 1.0f) * 0.5f * (float)(HH - 1);
    float x0f = floorf(x), y0f = floorf(y);
    float wx = x - x0f, wy = y - y0f;
    int x0 = (int)x0f, y0 = (int)y0f;

    float w00 = (1.0f - wx) * (1.0f - wy);
    float w10 = wx * (1.0f - wy);
    float w01 = (1.0f - wx) * wy;
    float w11 = wx * wy;

    float acc0 = 0.f, acc1 = 0.f, acc2 = 0.f, acc3 = 0.f, acc4 = 0.f;

    const int dxs[4] = {0, 1, 0, 1};
    const int dys[4] = {0, 0, 1, 1};
    const float wts[4] = {w00, w10, w01, w11};

    #pragma unroll
    for (int c = 0; c < 4; ++c) {
        int xi = x0 + dxs[c];
        int yi = y0 + dys[c];
        if (xi >= 0 && xi < WW && yi >= 0 && yi < HH) {
            int q = yi * WW + xi;
            float dux = duv[q * 2 + 0];
            float duy = duv[q * 2 + 1];
            float val = (fabsf(dux) <= 1.0f && fabsf(duy) <= 1.0f) ? 1.0f : 0.0f;
            float gx = xi * STEPC - 1.0f;
            float gy = yi * STEPC - 1.0f;
            float w = wts[c];
            acc0 += gx * w;
            acc1 += gy * w;
            acc2 += (dux - gx) * val * w;
            acc3 += (duy - gy) * val * w;
            acc4 += val * w;
        }
    }

    float mk = (acc4 > 0.5f) ? 1.0f : 0.0f;
    float* Wp = g_warp + n * 5 * HW;
    Wp[0 * HW + p] = acc0;
    Wp[1 * HW + p] = acc1;
    Wp[2 * HW + p] = acc2;
    Wp[3 * HW + p] = acc3;
    Wp[4 * HW + p] = mk;
    outMask[idx] = mk;
}

#define ACC4(acc, aa, bb) \
    acc.x = fmaf(aa, bb.x, acc.x); acc.y = fmaf(aa, bb.y, acc.y); \
    acc.z = fmaf(aa, bb.z, acc.z); acc.w = fmaf(aa, bb.w, acc.w);

// ---------------- half slab update: trisolve (8x8 blocked) + float4 GEMM ----------------
// updates block column B w.r.t. panel j. GEMM rows: interleaved 64-row tiles,
// starting at 64*(j+1) + 64*parity, stride 128.
__device__ void slab_update_half(float* A, int j, int B, int parity, bool storeU, int tid)
{
    extern __shared__ float smdyn[];
    float* sL = smdyn;            // 64x64 L11 (panel j)
    float* Bs = smdyn + 4096;     // 64x64 U12 slab
    float* As = smdyn + 8192;     // 64x64 L21 tile

    int k0 = 64 * j;
    int col0 = 64 * B;
    int w = NCOL - col0; if (w > 64) w = 64;
    int lo = k0 + 64;

    if (!storeU && lo + 64 * parity >= MM) return;   // nothing to do (uniform)

    for (int idx = tid; idx < 4096; idx += NTH) {
        int r = idx >> 6, c = idx & 63;
        sL[idx] = A[(k0 + r) * SRIDE + k0 + c];
        Bs[idx] = (c < w) ? A[(k0 + r) * SRIDE + col0 + c] : 0.0f;
    }
    __syncthreads();

    // blocked trisolve: U12 = L11^-1 * A12 (unit lower L, strictly-lower entries)
    #pragma unroll
    for (int ib = 0; ib < 8; ++ib) {
        int base = ib * 8;
        if (tid < 64) {
            int c = tid;
            float x[8];
            #pragma unroll
            for (int r = 0; r < 8; ++r) x[r] = Bs[(base + r) * 64 + c];
            #pragma unroll
            for (int i = 0; i < 8; ++i) {
                float xi = x[i];
                #pragma unroll
                for (int r = 0; r < 8; ++r)
                    if (r > i) x[r] = fmaf(-sL[(base + r) * 64 + base + i], xi, x[r]);
            }
            #pragma unroll
            for (int r = 1; r < 8; ++r) Bs[(base + r) * 64 + c] = x[r];
        }
        __syncthreads();
        if (base + 8 < 64) {
            int c = tid & 63;
            int g = tid >> 6;
            for (int jj = base + 8 + g; jj < 64; jj += 8) {
                float acc = Bs[jj * 64 + c];
                #pragma unroll
                for (int i = 0; i < 8; ++i)
                    acc = fmaf(-sL[jj * 64 + base + i], Bs[(base + i) * 64 + c], acc);
                Bs[jj * 64 + c] = acc;
            }
        }
        __syncthreads();
    }

    if (storeU) {
        for (int idx = tid; idx < 4096; idx += NTH) {
            int r = idx >> 6, c = idx & 63;
            if (c < w) A[(k0 + r) * SRIDE + col0 + c] = Bs[idx];
        }
    }

    // GEMM: A22 -= L21 * U12 over my interleaved 64-row tiles
    int c4 = (tid & 15) * 4;
    int r0 = (tid >> 4) * 2;
    int r1 = r0 + 1;
    for (int row0 = lo + 64 * parity; row0 < MM; row0 += 128) {
        int nrows = MM - row0; if (nrows > 64) nrows = 64;
        for (int idx = tid; idx < 4096; idx += NTH) {
            int r = idx >> 6, c = idx & 63;
            As[idx] = (r < nrows) ? A[(row0 + r) * SRIDE + k0 + c] : 0.0f;
        }
        __syncthreads();

        float4 acc0 = {0.f,0.f,0.f,0.f};
        float4 acc1 = {0.f,0.f,0.f,0.f};
        #pragma unroll
        for (int kk4 = 0; kk4 < 16; ++kk4) {
            float4 a0 = *(const float4*)&As[r0 * 64 + kk4 * 4];
            float4 a1 = *(const float4*)&As[r1 * 64 + kk4 * 4];
            const float* bb = &Bs[(kk4 * 4) * 64 + c4];
            float4 b0 = *(const float4*)(bb);
            float4 b1 = *(const float4*)(bb + 64);
            float4 b2 = *(const float4*)(bb + 128);
            float4 b3 = *(const float4*)(bb + 192);
            ACC4(acc0, a0.x, b0) ACC4(acc0, a0.y, b1) ACC4(acc0, a0.z, b2) ACC4(acc0, a0.w, b3)
            ACC4(acc1, a1.x, b0) ACC4(acc1, a1.y, b1) ACC4(acc1, a1.z, b2) ACC4(acc1, a1.w, b3)
        }

        if (w == 64) {
            if (r0 < nrows) {
                float4 v = *(float4*)&A[(row0 + r0) * SRIDE + col0 + c4];
                v.x -= acc0.x; v.y -= acc0.y; v.z -= acc0.z; v.w -= acc0.w;
                *(float4*)&A[(row0 + r0) * SRIDE + col0 + c4] = v;
            }
            if (r1 < nrows) {
                float4 v = *(float4*)&A[(row0 + r1) * SRIDE + col0 + c4];
                v.x -= acc1.x; v.y -= acc1.y; v.z -= acc1.z; v.w -= acc1.w;
                *(float4*)&A[(row0 + r1) * SRIDE + col0 + c4] = v;
            }
        } else {
            float a0a[4] = {acc0.x, acc0.y, acc0.z, acc0.w};
            float a1a[4] = {acc1.x, acc1.y, acc1.z, acc1.w};
            #pragma unroll
            for (int q = 0; q < 4; ++q) {
                int c = c4 + q;
                if (c < w) {
                    if (r0 < nrows) A[(row0 + r0) * SRIDE + col0 + c] -= a0a[q];
                    if (r1 < nrows) A[(row0 + r1) * SRIDE + col0 + c] -= a1a[q];
                }
            }
        }
        __syncthreads();
    }
}

__shared__ float s_piv[2][64];
__shared__ float s_pvi[2];

// ---------------- solver ----------------
__global__ void __launch_bounds__(NTH, 1) solve_kernel()
{
    extern __shared__ float smdyn[];
    int cta = blockIdx.x;
    int tid = threadIdx.x;
    int lane = tid & 31;
    int wid = tid >> 5;

    // ===== build: 144 CTAs, 24 per matrix =====
    {
        int n = cta % NBATCH;
        int part = cta / NBATCH;
        float* s_sx = smdyn;
        float* s_sy = smdyn + KC;
        float* s_m  = smdyn + 2 * KC;
        float* s_dx = smdyn + 3 * KC;
        float* s_dy = smdyn + 4 * KC;

        const float* Wp = g_warp + n * 5 * HW;
        for (int k = tid; k < KC; k += NTH) {
            int a = k / 20, b = k - a * 20;
            int ii = __double2int_rn(a * (191.0 / 19.0));
            int jj = __double2int_rn(b * (191.0 / 19.0));
            int p = ii * WW + jj;
            float sx = Wp[p];
            float sy = Wp[HW + p];
            float m  = Wp[4 * HW + p];
            s_sx[k] = sx; s_sy[k] = sy; s_m[k] = m;
            s_dx[k] = jj * STEPC - 1.0f;
            s_dy[k] = ii * STEPC - 1.0f;
            if (part == 0) {
                g_src[(n * KC + k) * 2 + 0] = sx;
                g_src[(n * KC + k) * 2 + 1] = sy;
            }
        }
        __syncthreads();

        float* A = g_A + n * MM * SRIDE;
        int r0 = part * 17;
        int r1 = min(MM, r0 + 17);
        for (int i = r0; i < r1; ++i) {
            for (int j = tid; j < NCOL; j += NTH) {
                float vout;
                if (i < KC) {
                    if (j < KC) {
                        float dx = s_sx[i] - s_sx[j];
                        float dy = s_sy[i] - s_sy[j];
                        float r2 = dx * dx + dy * dy;
                        vout = 0.5f * r2 * __logf(r2 + EPSV);
                        if (i == j) vout += LAMBDAV + BIGV * (1.0f - s_m[i]);
                    } else if (j == 400) vout = 1.0f;
                    else if (j == 401) vout = s_sx[i];
                    else if (j == 402) vout = s_sy[i];
                    else if (j == 403) vout = s_dx[i];
                    else               vout = s_dy[i];
                } else {
                    if (j < KC) {
                        vout = (i == 400) ? 1.0f : ((i == 401) ? s_sx[j] : s_sy[j]);
                    } else {
                        vout = 0.0f;
                    }
                }
                A[i * SRIDE + j] = vout;
            }
        }
        __threadfence();
        __syncthreads();
        if (tid == 0) atomicAdd(&g_buildcnt[n], 1u);
    }
    if (cta >= 72) return;
    __syncthreads();

    // ===== slab half CTAs: 12..71 =====
    if (cta >= 12) {
        int idx = cta - 12;
        int n = idx / 10;
        int rem = idx - n * 10;
        int B = 2 + rem / 2;
        int h = rem & 1;
        float* A = g_A + n * MM * SRIDE;
        for (int j = 0; j <= B - 2; ++j) {
            if (tid == 0) {
                while (ldv(&g_panelflag[n]) < (unsigned)(j + 1)) __nanosleep(64);
                while (ldv(&g_prog[n * 8 + B]) < (unsigned)(2 * j)) __nanosleep(64);
            }
            __syncthreads();
            __threadfence();
            slab_update_half(A, j, B, h, h == 0, tid);
            __threadfence();
            __syncthreads();
            if (tid == 0) atomicAdd(&g_prog[n * 8 + B], 1u);
        }
        return;
    }

    // ===== partner CTAs: 6..11 =====
    if (cta >= NBATCH) {
        int n = cta - NBATCH;
        float* A = g_A + n * MM * SRIDE;
        for (int k = 0; k < NPAN - 1; ++k) {
            int Bb = k + 1;
            if (tid == 0) {
                while (ldv(&g_panelflag[n]) < (unsigned)(k + 1)) __nanosleep(64);
                if (Bb >= 2) {
                    while (ldv(&g_prog[n * 8 + Bb]) < (unsigned)(2 * k)) __nanosleep(64);
                }
            }
            __syncthreads();
            __threadfence();
            slab_update_half(A, k, Bb, 1, false, tid);
            __threadfence();
            __syncthreads();
            if (tid == 0) atomicExch(&g_prog2[n], (unsigned)(k + 1));
        }
        return;
    }

    // ===== panel CTAs: 0..5 =====
    int n = cta;
    float* A = g_A + n * MM * SRIDE;

    if (tid == 0) { while (ldv(&g_buildcnt[n]) < 24u) __nanosleep(64); }
    __syncthreads();
    __threadfence();

    for (int k = 0; k < NPAN; ++k) {
        int k0 = 64 * k;
        int nb = MM - k0; if (nb > 64) nb = 64;
        int R  = MM - k0;
        bool active = (tid < R);

        // register-resident panel factorization (no pivoting)
        float rgv[64];
        {
            const float* rowp = A + (k0 + tid) * SRIDE + k0;
            if (active) {
                if (nb == 64) {
                    #pragma unroll
                    for (int c4 = 0; c4 < 64; c4 += 4) {
                        float4 v = *(const float4*)&rowp[c4];
                        rgv[c4 + 0] = v.x; rgv[c4 + 1] = v.y;
                        rgv[c4 + 2] = v.z; rgv[c4 + 3] = v.w;
                    }
                } else {
                    #pragma unroll
                    for (int c = 0; c < 64; ++c) rgv[c] = (c < nb) ? rowp[c] : 0.0f;
                }
            }
        }
        float nextm = rgv[0];

        for (int j = 0; j < nb; ++j) {
            int jb = j & 1;
            if (tid == j) {
                #pragma unroll
                for (int c = 0; c < 64; ++c) s_piv[jb][c] = rgv[c];
                s_pvi[jb] = 1.0f / nextm;
            }
            __syncthreads();
            if (active && tid > j) {
                float m = nextm * s_pvi[jb];
                float nm2 = 0.0f;
                #pragma unroll
                for (int c = 0; c < 64; ++c) {
                    if (c > j) {
                        rgv[c] = fmaf(-m, s_piv[jb][c], rgv[c]);
                        if (c == j + 1) nm2 = rgv[c];
                    } else if (c == j) {
                        rgv[c] = m;
                    }
                }
                nextm = nm2;
            }
        }

        if (active) {
            float* rowp = A + (k0 + tid) * SRIDE + k0;
            if (nb == 64) {
                #pragma unroll
                for (int c4 = 0; c4 < 64; c4 += 4) {
                    float4 v;
                    v.x = rgv[c4 + 0]; v.y = rgv[c4 + 1];
                    v.z = rgv[c4 + 2]; v.w = rgv[c4 + 3];
                    *(float4*)&rowp[c4] = v;
                }
            } else {
                #pragma unroll
                for (int c = 0; c < 64; ++c) if (c < nb) rowp[c] = rgv[c];
            }
        }
        __threadfence();
        __syncthreads();
        if (tid == 0) atomicExch(&g_panelflag[n], (unsigned)(k + 1));

        if (k < NPAN - 1) {
            int Bb = k + 1;
            if (Bb >= 2) {
                if (tid == 0) { while (ldv(&g_prog[n * 8 + Bb]) < (unsigned)(2 * k)) __nanosleep(64); }
                __syncthreads();
                __threadfence();
            }
            slab_update_half(A, k, Bb, 0, true, tid);
            __syncthreads();
            if (tid == 0) { while (ldv(&g_prog2[n]) < (unsigned)(k + 1)) __nanosleep(64); }
            __syncthreads();
            __threadfence();
        } else {
            // trisolve RHS cols 403,404 (rows 384..402) wrt unit-lower L of panel 6
            float* sL = smdyn;
            for (int idx = tid; idx < 19 * 19; idx += NTH) {
                int r = idx / 19, c = idx - r * 19;
                sL[r * 64 + c] = A[(384 + r) * SRIDE + 384 + c];
            }
            __syncthreads();
            if (tid < 2) {
                float x[19];
                float* colp = A + 384 * SRIDE + 403 + tid;
                #pragma unroll
                for (int r = 0; r < 19; ++r) x[r] = colp[r * SRIDE];
                #pragma unroll
                for (int i = 0; i < 19; ++i) {
                    float xi = x[i];
                    #pragma unroll
                    for (int jj = i + 1; jj < 19; ++jj)
                        x[jj] = fmaf(-sL[jj * 64 + i], xi, x[jj]);
                }
                #pragma unroll
                for (int r = 0; r < 19; ++r) colp[r * SRIDE] = x[r];
            }
            __syncthreads();
        }
    }

    // ===== back-substitution =====
    {
        float* sD  = smdyn;              // 64x65
        float* x0s = smdyn + 4160;       // MM
        float* x1s = x0s + MM;

        for (int j = tid; j < MM; j += NTH) {
            x0s[j] = A[j * SRIDE + 403];
            x1s[j] = A[j * SRIDE + 404];
        }
        __syncthreads();

        for (int b = 6; b >= 0; --b) {
            int bk0 = b * 64;
            int bnb = (MM - bk0 < 64) ? (MM - bk0) : 64;

            for (int idx = tid; idx < bnb * bnb; idx += NTH) {
                int r = idx / bnb, cc = idx - r * bnb;
                sD[r * 65 + cc] = A[(bk0 + r) * SRIDE + bk0 + cc];
            }
            __syncthreads();

            if (wid == 0) {
                for (int k = bnb - 1; k >= 0; --k) {
                    float s0 = 0.f, s1 = 0.f;
                    for (int j = k + 1 + lane; j < bnb; j += 32) {
                        float u = sD[k * 65 + j];
                        s0 = fmaf(u, x0s[bk0 + j], s0);
                        s1 = fmaf(u, x1s[bk0 + j], s1);
                    }
                    #pragma unroll
                    for (int off = 16; off > 0; off >>= 1) {
                        s0 += __shfl_down_sync(0xffffffffu, s0, off);
                        s1 += __shfl_down_sync(0xffffffffu, s1, off);
                    }
                    if (lane == 0) {
                        float d = 1.0f / sD[k * 65 + k];
                        x0s[bk0 + k] = (x0s[bk0 + k] - s0) * d;
                        x1s[bk0 + k] = (x1s[bk0 + k] - s1) * d;
                    }
                    __syncwarp();
                }
            }
            __syncthreads();

            for (int r = tid; r < bk0; r += NTH) {
                float s0 = 0.f, s1 = 0.f;
                const float* Ur = A + r * SRIDE + bk0;
                #pragma unroll 8
                for (int j = 0; j < bnb; ++j) {
                    float u = Ur[j];
                    s0 = fmaf(u, x0s[bk0 + j], s0);
                    s1 = fmaf(u, x1s[bk0 + j], s1);
                }
                x0s[r] -= s0;
                x1s[r] -= s1;
            }
            __syncthreads();
        }

        for (int j = tid; j < MM; j += NTH) {
            g_sol[(n * MM + j) * 2 + 0] = x0s[j];
            g_sol[(n * MM + j) * 2 + 1] = x1s[j];
        }
    }
}

// ---------------- Stage 4: TPS evaluation + Jacobian + output ----------------
__global__ void __launch_bounds__(256) eval_kernel(float* __restrict__ outDef)
{
    int n = blockIdx.y;
    int p = blockIdx.x * blockDim.x + threadIdx.x;
    int tid = threadIdx.x;

    __shared__ float4 s_sw[KC];
    __shared__ float s_aff[6];

    for (int k = tid; k < KC; k += blockDim.x) {
        float4 t;
        t.x = g_src[(n * KC + k) * 2 + 0];
        t.y = g_src[(n * KC + k) * 2 + 1];
        t.z = g_sol[(n * MM + k) * 2 + 0] * HALF_LN2;
        t.w = g_sol[(n * MM + k) * 2 + 1] * HALF_LN2;
        s_sw[k] = t;
    }
    if (tid < 6) s_aff[tid] = g_sol[(n * MM + 400) * 2 + tid];
    __syncthreads();

    const float* Wp = g_warp + n * 5 * HW;
    float q0x = Wp[p];
    float q0y = Wp[HW + p];
    float dlx = Wp[2 * HW + p];
    float dly = Wp[3 * HW + p];
    float mk  = Wp[4 * HW + p];

    float a0x = 0.f, a0y = 0.f, a1x = 0.f, a1y = 0.f, a2x = 0.f, a2y = 0.f;

    #pragma unroll 4
    for (int k = 0; k < KC; ++k) {
        float4 s = s_sw[k];
        float d0x = q0x - s.x;
        float d0y = q0y - s.y;
        float e0x = fmaf(2.0f, d0x, STEPC);
        float e0y = fmaf(2.0f, d0y, STEPC);
        float r0 = fmaf(d0x, d0x, d0y * d0y) + EPSV;
        float r1 = fmaf(STEPC, e0x, r0);
        float r2 = fmaf(STEPC, e0y, r0);
        float u0 = r0 * __log2f(r0);
        float u1 = r1 * __log2f(r1);
        float u2 = r2 * __log2f(r2);
        a0x = fmaf(u0, s.z, a0x);  a0y = fmaf(u0, s.w, a0y);
        a1x = fmaf(u1, s.z, a1x);  a1y = fmaf(u1, s.w, a1y);
        a2x = fmaf(u2, s.z, a2x);  a2y = fmaf(u2, s.w, a2y);
    }

    float q1x = q0x + STEPC;
    float q2y = q0y + STEPC;
    float c0x = a0x + s_aff[0] + s_aff[2] * q0x + s_aff[4] * q0y;
    float c0y = a0y + s_aff[1] + s_aff[3] * q0x + s_aff[5] * q0y;
    float c1x = a1x + s_aff[0] + s_aff[2] * q1x + s_aff[4] * q0y;
    float c1y = a1y + s_aff[1] + s_aff[3] * q1x + s_aff[5] * q0y;
    float c2x = a2x + s_aff[0] + s_aff[2] * q0x + s_aff[4] * q2y;
    float c2y = a2y + s_aff[1] + s_aff[3] * q0x + s_aff[5] * q2y;

    float ja = (c1x - c0x) / STEPC;
    float jb = (c1y - c0y) / STEPC;
    float jc = (c2x - c0x) / STEPC;
    float jd = (c2y - c0y) / STEPC;

    float dnx = ja * dlx + jc * dly;
    float dny = jb * dlx + jd * dly;

    int i = p / WW;
    int j = p - i * WW;
    float gx = j * STEPC - 1.0f;
    float gy = i * STEPC - 1.0f;
    float dfx = (gx + dnx) * mk - 2.0f * (1.0f - mk);
    float dfy = (gy + dny) * mk - 2.0f * (1.0f - mk);

    outDef[(n * HW + p) * 2 + 0] = dfx;
    outDef[(n * HW + p) * 2 + 1] = dfy;
}

// ---------------- launch ----------------
extern "C" void kernel_launch(void* const* d_in, const int* in_sizes, int n_in,
                              void* d_out, int out_size)
{
    const float* a0 = (const float*)d_in[0];
    const float* a1 = (const float*)d_in[1];
    const float* duv;
    const float* uv;
    if (in_sizes[0] == 2 * HW) { duv = a0; uv = a1; }
    else                        { duv = a1; uv = a0; }

    float* out = (float*)d_out;
    float* outDef  = out;
    float* outMask = out + NBATCH * HW * 2;

    const int SMBYTES = 12288 * (int)sizeof(float);   // 48 KB dynamic
    cudaFuncSetAttribute(solve_kernel,
                         cudaFuncAttributeMaxDynamicSharedMemorySize, SMBYTES);

    warp_kernel<<<(NBATCH * HW + 255) / 256, 256>>>(duv, uv, outMask);
    solve_kernel<<<144, NTH, SMBYTES>>>();
    eval_kernel<<<dim3(HW / 256, NBATCH), 256>>>(outDef);
}

// round 8
// speedup vs baseline: 1.7284x; 1.0358x over previous
#include <cuda_runtime.h>
#include <math.h>

#define HH 192
#define WW 192
#define HW (HH*WW)
#define NBATCH 6
#define KC 400
#define MM 403
#define NCOL 405
#define SRIDE 416
#define LAMBDAV 100.0f
#define BIGV 1.0e8f
#define EPSV 1.0e-9f
#define STEPC (2.0f/191.0f)
#define HALF_LN2 0.34657359028f
#define NTH 512
#define NPAN 7

// ---------------- device scratch ----------------
__device__ float g_A[NBATCH * MM * SRIDE];
__device__ float g_warp[NBATCH * 5 * HW];
__device__ float g_src[NBATCH * KC * 2];
__device__ float g_sol[NBATCH * MM * 2];
__device__ unsigned g_buildcnt[NBATCH];
__device__ unsigned g_panelflag[NBATCH];
__device__ unsigned g_prog[NBATCH * 8];
__device__ unsigned g_prog2[NBATCH];

__device__ __forceinline__ unsigned ldv(unsigned* p) { return *(volatile unsigned*)p; }

// ---------------- Stage 1: backward warp (+ flag reset) ----------------
__global__ void warp_kernel(const float* __restrict__ duv,
                            const float* __restrict__ uv,
                            float* __restrict__ outMask)
{
    if (blockIdx.x == 0) {
        if (threadIdx.x < NBATCH) {
            g_buildcnt[threadIdx.x] = 0;
            g_panelflag[threadIdx.x] = 0;
            g_prog2[threadIdx.x] = 0;
        }
        if (threadIdx.x < NBATCH * 8) g_prog[threadIdx.x] = 0;
    }

    int idx = blockIdx.x * blockDim.x + threadIdx.x;
    if (idx >= NBATCH * HW) return;
    int n = idx / HW;
    int p = idx - n * HW;

    float u = uv[idx * 2 + 0];
    float v = uv[idx * 2 + 1];
    float x = (u + 1.0f) * 0.5f * (float)(WW - 1);
    float y = (v + 1.0f) * 0.5f * (float)(HH - 1);
    float x0f = floorf(x), y0f = floorf(y);
    float wx = x - x0f, wy = y - y0f;
    int x0 = (int)x0f, y0 = (int)y0f;

    float w00 = (1.0f - wx) * (1.0f - wy);
    float w10 = wx * (1.0f - wy);
    float w01 = (1.0f - wx) * wy;
    float w11 = wx * wy;

    float acc0 = 0.f, acc1 = 0.f, acc2 = 0.f, acc3 = 0.f, acc4 = 0.f;

    const int dxs[4] = {0, 1, 0, 1};
    const int dys[4] = {0, 0, 1, 1};
    const float wts[4] = {w00, w10, w01, w11};

    #pragma unroll
    for (int c = 0; c < 4; ++c) {
        int xi = x0 + dxs[c];
        int yi = y0 + dys[c];
        if (xi >= 0 && xi < WW && yi >= 0 && yi < HH) {
            int q = yi * WW + xi;
            float dux = duv[q * 2 + 0];
            float duy = duv[q * 2 + 1];
            float val = (fabsf(dux) <= 1.0f && fabsf(duy) <= 1.0f) ? 1.0f : 0.0f;
            float gx = xi * STEPC - 1.0f;
            float gy = yi * STEPC - 1.0f;
            float w = wts[c];
            acc0 += gx * w;
            acc1 += gy * w;
            acc2 += (dux - gx) * val * w;
            acc3 += (duy - gy) * val * w;
            acc4 += val * w;
        }
    }

    float mk = (acc4 > 0.5f) ? 1.0f : 0.0f;
    float* Wp = g_warp + n * 5 * HW;
    Wp[0 * HW + p] = acc0;
    Wp[1 * HW + p] = acc1;
    Wp[2 * HW + p] = acc2;
    Wp[3 * HW + p] = acc3;
    Wp[4 * HW + p] = mk;
    outMask[idx] = mk;
}

#define ACC4(acc, aa, bb) \
    acc.x = fmaf(aa, bb.x, acc.x); acc.y = fmaf(aa, bb.y, acc.y); \
    acc.z = fmaf(aa, bb.z, acc.z); acc.w = fmaf(aa, bb.w, acc.w);

// ---------------- half slab update: trisolve (8x8 blocked) + float4 GEMM ----------------
__device__ void slab_update_half(float* A, int j, int B, int parity, bool storeU, int tid)
{
    extern __shared__ float smdyn[];
    float* sL = smdyn;            // 64x64 L11 (panel j)
    float* Bs = smdyn + 4096;     // 64x64 U12 slab
    float* As = smdyn + 8192;     // 64x64 L21 tile

    int k0 = 64 * j;
    int col0 = 64 * B;
    int w = NCOL - col0; if (w > 64) w = 64;
    int lo = k0 + 64;

    if (!storeU && lo + 64 * parity >= MM) return;

    for (int idx = tid; idx < 4096; idx += NTH) {
        int r = idx >> 6, c = idx & 63;
        sL[idx] = A[(k0 + r) * SRIDE + k0 + c];
        Bs[idx] = (c < w) ? A[(k0 + r) * SRIDE + col0 + c] : 0.0f;
    }
    __syncthreads();

    #pragma unroll
    for (int ib = 0; ib < 8; ++ib) {
        int base = ib * 8;
        if (tid < 64) {
            int c = tid;
            float x[8];
            #pragma unroll
            for (int r = 0; r < 8; ++r) x[r] = Bs[(base + r) * 64 + c];
            #pragma unroll
            for (int i = 0; i < 8; ++i) {
                float xi = x[i];
                #pragma unroll
                for (int r = 0; r < 8; ++r)
                    if (r > i) x[r] = fmaf(-sL[(base + r) * 64 + base + i], xi, x[r]);
            }
            #pragma unroll
            for (int r = 1; r < 8; ++r) Bs[(base + r) * 64 + c] = x[r];
        }
        __syncthreads();
        if (base + 8 < 64) {
            int c = tid & 63;
            int g = tid >> 6;
            for (int jj = base + 8 + g; jj < 64; jj += 8) {
                float acc = Bs[jj * 64 + c];
                #pragma unroll
                for (int i = 0; i < 8; ++i)
                    acc = fmaf(-sL[jj * 64 + base + i], Bs[(base + i) * 64 + c], acc);
                Bs[jj * 64 + c] = acc;
            }
        }
        __syncthreads();
    }

    if (storeU) {
        for (int idx = tid; idx < 4096; idx += NTH) {
            int r = idx >> 6, c = idx & 63;
            if (c < w) A[(k0 + r) * SRIDE + col0 + c] = Bs[idx];
        }
    }

    int c4 = (tid & 15) * 4;
    int r0 = (tid >> 4) * 2;
    int r1 = r0 + 1;
    for (int row0 = lo + 64 * parity; row0 < MM; row0 += 128) {
        int nrows = MM - row0; if (nrows > 64) nrows = 64;
        for (int idx = tid; idx < 4096; idx += NTH) {
            int r = idx >> 6, c = idx & 63;
            As[idx] = (r < nrows) ? A[(row0 + r) * SRIDE + k0 + c] : 0.0f;
        }
        __syncthreads();

        float4 acc0 = {0.f,0.f,0.f,0.f};
        float4 acc1 = {0.f,0.f,0.f,0.f};
        #pragma unroll
        for (int kk4 = 0; kk4 < 16; ++kk4) {
            float4 a0 = *(const float4*)&As[r0 * 64 + kk4 * 4];
            float4 a1 = *(const float4*)&As[r1 * 64 + kk4 * 4];
            const float* bb = &Bs[(kk4 * 4) * 64 + c4];
            float4 b0 = *(const float4*)(bb);
            float4 b1 = *(const float4*)(bb + 64);
            float4 b2 = *(const float4*)(bb + 128);
            float4 b3 = *(const float4*)(bb + 192);
            ACC4(acc0, a0.x, b0) ACC4(acc0, a0.y, b1) ACC4(acc0, a0.z, b2) ACC4(acc0, a0.w, b3)
            ACC4(acc1, a1.x, b0) ACC4(acc1, a1.y, b1) ACC4(acc1, a1.z, b2) ACC4(acc1, a1.w, b3)
        }

        if (w == 64) {
            if (r0 < nrows) {
                float4 v = *(float4*)&A[(row0 + r0) * SRIDE + col0 + c4];
                v.x -= acc0.x; v.y -= acc0.y; v.z -= acc0.z; v.w -= acc0.w;
                *(float4*)&A[(row0 + r0) * SRIDE + col0 + c4] = v;
            }
            if (r1 < nrows) {
                float4 v = *(float4*)&A[(row0 + r1) * SRIDE + col0 + c4];
                v.x -= acc1.x; v.y -= acc1.y; v.z -= acc1.z; v.w -= acc1.w;
                *(float4*)&A[(row0 + r1) * SRIDE + col0 + c4] = v;
            }
        } else {
            float a0a[4] = {acc0.x, acc0.y, acc0.z, acc0.w};
            float a1a[4] = {acc1.x, acc1.y, acc1.z, acc1.w};
            #pragma unroll
            for (int q = 0; q < 4; ++q) {
                int c = c4 + q;
                if (c < w) {
                    if (r0 < nrows) A[(row0 + r0) * SRIDE + col0 + c] -= a0a[q];
                    if (r1 < nrows) A[(row0 + r1) * SRIDE + col0 + c] -= a1a[q];
                }
            }
        }
        __syncthreads();
    }
}

// ---------------- solver ----------------
__global__ void __launch_bounds__(NTH, 1) solve_kernel()
{
    extern __shared__ float smdyn[];
    int cta = blockIdx.x;
    int tid = threadIdx.x;
    int lane = tid & 31;
    int wid = tid >> 5;

    // ===== build: 144 CTAs, 24 per matrix =====
    {
        int n = cta % NBATCH;
        int part = cta / NBATCH;
        float* s_sx = smdyn;
        float* s_sy = smdyn + KC;
        float* s_m  = smdyn + 2 * KC;
        float* s_dx = smdyn + 3 * KC;
        float* s_dy = smdyn + 4 * KC;

        const float* Wp = g_warp + n * 5 * HW;
        for (int k = tid; k < KC; k += NTH) {
            int a = k / 20, b = k - a * 20;
            int ii = __double2int_rn(a * (191.0 / 19.0));
            int jj = __double2int_rn(b * (191.0 / 19.0));
            int p = ii * WW + jj;
            float sx = Wp[p];
            float sy = Wp[HW + p];
            float m  = Wp[4 * HW + p];
            s_sx[k] = sx; s_sy[k] = sy; s_m[k] = m;
            s_dx[k] = jj * STEPC - 1.0f;
            s_dy[k] = ii * STEPC - 1.0f;
            if (part == 0) {
                g_src[(n * KC + k) * 2 + 0] = sx;
                g_src[(n * KC + k) * 2 + 1] = sy;
            }
        }
        __syncthreads();

        float* A = g_A + n * MM * SRIDE;
        int r0 = part * 17;
        int r1 = min(MM, r0 + 17);
        for (int i = r0; i < r1; ++i) {
            for (int j = tid; j < NCOL; j += NTH) {
                float vout;
                if (i < KC) {
                    if (j < KC) {
                        float dx = s_sx[i] - s_sx[j];
                        float dy = s_sy[i] - s_sy[j];
                        float r2 = dx * dx + dy * dy;
                        vout = 0.5f * r2 * __logf(r2 + EPSV);
                        if (i == j) vout += LAMBDAV + BIGV * (1.0f - s_m[i]);
                    } else if (j == 400) vout = 1.0f;
                    else if (j == 401) vout = s_sx[i];
                    else if (j == 402) vout = s_sy[i];
                    else if (j == 403) vout = s_dx[i];
                    else               vout = s_dy[i];
                } else {
                    if (j < KC) {
                        vout = (i == 400) ? 1.0f : ((i == 401) ? s_sx[j] : s_sy[j]);
                    } else {
                        vout = 0.0f;
                    }
                }
                A[i * SRIDE + j] = vout;
            }
        }
        __threadfence();
        __syncthreads();
        if (tid == 0) atomicAdd(&g_buildcnt[n], 1u);
    }
    if (cta >= 72) return;
    __syncthreads();

    // ===== slab half CTAs: 12..71 =====
    if (cta >= 12) {
        int idx = cta - 12;
        int n = idx / 10;
        int rem = idx - n * 10;
        int B = 2 + rem / 2;
        int h = rem & 1;
        float* A = g_A + n * MM * SRIDE;
        for (int j = 0; j <= B - 2; ++j) {
            if (tid == 0) {
                while (ldv(&g_panelflag[n]) < (unsigned)(j + 1)) __nanosleep(64);
                while (ldv(&g_prog[n * 8 + B]) < (unsigned)(2 * j)) __nanosleep(64);
            }
            __syncthreads();
            __threadfence();
            slab_update_half(A, j, B, h, h == 0, tid);
            __threadfence();
            __syncthreads();
            if (tid == 0) atomicAdd(&g_prog[n * 8 + B], 1u);
        }
        return;
    }

    // ===== partner CTAs: 6..11 =====
    if (cta >= NBATCH) {
        int n = cta - NBATCH;
        float* A = g_A + n * MM * SRIDE;
        for (int k = 0; k < NPAN - 1; ++k) {
            int Bb = k + 1;
            if (tid == 0) {
                while (ldv(&g_panelflag[n]) < (unsigned)(k + 1)) __nanosleep(64);
                if (Bb >= 2) {
                    while (ldv(&g_prog[n * 8 + Bb]) < (unsigned)(2 * k)) __nanosleep(64);
                }
            }
            __syncthreads();
            __threadfence();
            slab_update_half(A, k, Bb, 1, false, tid);
            __threadfence();
            __syncthreads();
            if (tid == 0) atomicExch(&g_prog2[n], (unsigned)(k + 1));
        }
        return;
    }

    // ===== panel CTAs: 0..5 =====
    int n = cta;
    float* A = g_A + n * MM * SRIDE;

    if (tid == 0) { while (ldv(&g_buildcnt[n]) < 24u) __nanosleep(64); }
    __syncthreads();
    __threadfence();

    float* sD    = smdyn;            // 64 x 65 diag block
    float* sdinv = smdyn + 4160;     // 64 reciprocal diagonals

    for (int k = 0; k < NPAN; ++k) {
        int k0 = 64 * k;
        int nb = MM - k0; if (nb > 64) nb = 64;
        int R  = MM - k0;

        // ---- diag block factorization in smem ----
        for (int idx = tid; idx < nb * nb; idx += NTH) {
            int r = idx / nb, c = idx - r * nb;
            sD[r * 65 + c] = A[(k0 + r) * SRIDE + k0 + c];
        }
        __syncthreads();

        for (int j = 0; j < nb - 1; ++j) {
            if (tid > j && tid < nb) {
                float m = sD[tid * 65 + j] * __fdividef(1.0f, sD[j * 65 + j]);
                sD[tid * 65 + j] = m;
            }
            __syncthreads();
            {
                int r = tid & 63;
                int cg = tid >> 6;
                if (r > j && r < nb) {
                    float m = sD[r * 65 + j];
                    for (int c = j + 1 + cg; c < nb; c += 8)
                        sD[r * 65 + c] = fmaf(-m, sD[j * 65 + c], sD[r * 65 + c]);
                }
            }
            __syncthreads();
        }

        if (tid < nb) sdinv[tid] = __fdividef(1.0f, sD[tid * 65 + tid]);
        for (int idx = tid; idx < nb * nb; idx += NTH) {
            int r = idx / nb, c = idx - r * nb;
            A[(k0 + r) * SRIDE + k0 + c] = sD[r * 65 + c];
        }
        __syncthreads();

        // ---- L21 = A21 * U11^-1 : per-thread independent row solve (8-col blocks) ----
        if (nb == 64 && tid < R - 64) {
            float* rowp = A + (k0 + 64 + tid) * SRIDE + k0;
            #pragma unroll 1
            for (int jb = 0; jb < 8; ++jb) {
                int J0 = jb * 8;
                float x[8];
                #pragma unroll
                for (int q = 0; q < 8; ++q) x[q] = rowp[J0 + q];
                for (int i = 0; i < J0; ++i) {
                    float li = rowp[i];
                    const float* urow = &sD[i * 65 + J0];
                    #pragma unroll
                    for (int q = 0; q < 8; ++q) x[q] = fmaf(-li, urow[q], x[q]);
                }
                #pragma unroll
                for (int i = 0; i < 8; ++i) {
                    float xi = x[i] * sdinv[J0 + i];
                    x[i] = xi;
                    const float* urow = &sD[(J0 + i) * 65 + J0];
                    #pragma unroll
                    for (int q = 0; q < 8; ++q)
                        if (q > i) x[q] = fmaf(-xi, urow[q], x[q]);
                }
                #pragma unroll
                for (int q = 0; q < 8; ++q) rowp[J0 + q] = x[q];
            }
        }
        __threadfence();
        __syncthreads();
        if (tid == 0) atomicExch(&g_panelflag[n], (unsigned)(k + 1));

        if (k < NPAN - 1) {
            int Bb = k + 1;
            if (Bb >= 2) {
                if (tid == 0) { while (ldv(&g_prog[n * 8 + Bb]) < (unsigned)(2 * k)) __nanosleep(64); }
                __syncthreads();
                __threadfence();
            }
            slab_update_half(A, k, Bb, 0, true, tid);
            __syncthreads();
            if (tid == 0) { while (ldv(&g_prog2[n]) < (unsigned)(k + 1)) __nanosleep(64); }
            __syncthreads();
            __threadfence();
        } else {
            // trisolve RHS cols 403,404 (rows 384..402) wrt unit-lower L of panel 6
            float* sL = smdyn;
            __syncthreads();
            for (int idx = tid; idx < 19 * 19; idx += NTH) {
                int r = idx / 19, c = idx - r * 19;
                sL[r * 64 + c] = A[(384 + r) * SRIDE + 384 + c];
            }
            __syncthreads();
            if (tid < 2) {
                float x[19];
                float* colp = A + 384 * SRIDE + 403 + tid;
                #pragma unroll
                for (int r = 0; r < 19; ++r) x[r] = colp[r * SRIDE];
                #pragma unroll
                for (int i = 0; i < 19; ++i) {
                    float xi = x[i];
                    #pragma unroll
                    for (int jj = i + 1; jj < 19; ++jj)
                        x[jj] = fmaf(-sL[jj * 64 + i], xi, x[jj]);
                }
                #pragma unroll
                for (int r = 0; r < 19; ++r) colp[r * SRIDE] = x[r];
            }
            __syncthreads();
        }
    }

    // ===== back-substitution =====
    {
        float* x0s = smdyn + 4288;       // MM
        float* x1s = x0s + MM;
        float* sB  = smdyn;              // 64x65 reuse

        for (int j = tid; j < MM; j += NTH) {
            x0s[j] = A[j * SRIDE + 403];
            x1s[j] = A[j * SRIDE + 404];
        }
        __syncthreads();

        for (int b = 6; b >= 0; --b) {
            int bk0 = b * 64;
            int bnb = (MM - bk0 < 64) ? (MM - bk0) : 64;

            for (int idx = tid; idx < bnb * bnb; idx += NTH) {
                int r = idx / bnb, cc = idx - r * bnb;
                sB[r * 65 + cc] = A[(bk0 + r) * SRIDE + bk0 + cc];
            }
            __syncthreads();

            if (wid == 0) {
                for (int k = bnb - 1; k >= 0; --k) {
                    float s0 = 0.f, s1 = 0.f;
                    for (int j = k + 1 + lane; j < bnb; j += 32) {
                        float u = sB[k * 65 + j];
                        s0 = fmaf(u, x0s[bk0 + j], s0);
                        s1 = fmaf(u, x1s[bk0 + j], s1);
                    }
                    #pragma unroll
                    for (int off = 16; off > 0; off >>= 1) {
                        s0 += __shfl_down_sync(0xffffffffu, s0, off);
                        s1 += __shfl_down_sync(0xffffffffu, s1, off);
                    }
                    if (lane == 0) {
                        float d = 1.0f / sB[k * 65 + k];
                        x0s[bk0 + k] = (x0s[bk0 + k] - s0) * d;
                        x1s[bk0 + k] = (x1s[bk0 + k] - s1) * d;
                    }
                    __syncwarp();
                }
            }
            __syncthreads();

            for (int r = tid; r < bk0; r += NTH) {
                float s0 = 0.f, s1 = 0.f;
                const float* Ur = A + r * SRIDE + bk0;
                #pragma unroll 8
                for (int j = 0; j < bnb; ++j) {
                    float u = Ur[j];
                    s0 = fmaf(u, x0s[bk0 + j], s0);
                    s1 = fmaf(u, x1s[bk0 + j], s1);
                }
                x0s[r] -= s0;
                x1s[r] -= s1;
            }
            __syncthreads();
        }

        for (int j = tid; j < MM; j += NTH) {
            g_sol[(n * MM + j) * 2 + 0] = x0s[j];
            g_sol[(n * MM + j) * 2 + 1] = x1s[j];
        }
    }
}

// ---------------- Stage 4: TPS evaluation + Jacobian + output ----------------
__global__ void __launch_bounds__(256) eval_kernel(float* __restrict__ outDef)
{
    int n = blockIdx.y;
    int p = blockIdx.x * blockDim.x + threadIdx.x;
    int tid = threadIdx.x;

    __shared__ float4 s_sw[KC];
    __shared__ float s_aff[6];

    for (int k = tid; k < KC; k += blockDim.x) {
        float4 t;
        t.x = g_src[(n * KC + k) * 2 + 0];
        t.y = g_src[(n * KC + k) * 2 + 1];
        t.z = g_sol[(n * MM + k) * 2 + 0] * HALF_LN2;
        t.w = g_sol[(n * MM + k) * 2 + 1] * HALF_LN2;
        s_sw[k] = t;
    }
    if (tid < 6) s_aff[tid] = g_sol[(n * MM + 400) * 2 + tid];
    __syncthreads();

    const float* Wp = g_warp + n * 5 * HW;
    float q0x = Wp[p];
    float q0y = Wp[HW + p];
    float dlx = Wp[2 * HW + p];
    float dly = Wp[3 * HW + p];
    float mk  = Wp[4 * HW + p];

    float a0x = 0.f, a0y = 0.f, a1x = 0.f, a1y = 0.f, a2x = 0.f, a2y = 0.f;

    #pragma unroll 4
    for (int k = 0; k < KC; ++k) {
        float4 s = s_sw[k];
        float d0x = q0x - s.x;
        float d0y = q0y - s.y;
        float e0x = fmaf(2.0f, d0x, STEPC);
        float e0y = fmaf(2.0f, d0y, STEPC);
        float r0 = fmaf(d0x, d0x, d0y * d0y) + EPSV;
        float r1 = fmaf(STEPC, e0x, r0);
        float r2 = fmaf(STEPC, e0y, r0);
        float u0 = r0 * __log2f(r0);
        float u1 = r1 * __log2f(r1);
        float u2 = r2 * __log2f(r2);
        a0x = fmaf(u0, s.z, a0x);  a0y = fmaf(u0, s.w, a0y);
        a1x = fmaf(u1, s.z, a1x);  a1y = fmaf(u1, s.w, a1y);
        a2x = fmaf(u2, s.z, a2x);  a2y = fmaf(u2, s.w, a2y);
    }

    float q1x = q0x + STEPC;
    float q2y = q0y + STEPC;
    float c0x = a0x + s_aff[0] + s_aff[2] * q0x + s_aff[4] * q0y;
    float c0y = a0y + s_aff[1] + s_aff[3] * q0x + s_aff[5] * q0y;
    float c1x = a1x + s_aff[0] + s_aff[2] * q1x + s_aff[4] * q0y;
    float c1y = a1y + s_aff[1] + s_aff[3] * q1x + s_aff[5] * q0y;
    float c2x = a2x + s_aff[0] + s_aff[2] * q0x + s_aff[4] * q2y;
    float c2y = a2y + s_aff[1] + s_aff[3] * q0x + s_aff[5] * q2y;

    float ja = (c1x - c0x) / STEPC;
    float jb = (c1y - c0y) / STEPC;
    float jc = (c2x - c0x) / STEPC;
    float jd = (c2y - c0y) / STEPC;

    float dnx = ja * dlx + jc * dly;
    float dny = jb * dlx + jd * dly;

    int i = p / WW;
    int j = p - i * WW;
    float gx = j * STEPC - 1.0f;
    float gy = i * STEPC - 1.0f;
    float dfx = (gx + dnx) * mk - 2.0f * (1.0f - mk);
    float dfy = (gy + dny) * mk - 2.0f * (1.0f - mk);

    outDef[(n * HW + p) * 2 + 0] = dfx;
    outDef[(n * HW + p) * 2 + 1] = dfy;
}

// ---------------- launch ----------------
extern "C" void kernel_launch(void* const* d_in, const int* in_sizes, int n_in,
                              void* d_out, int out_size)
{
    const float* a0 = (const float*)d_in[0];
    const float* a1 = (const float*)d_in[1];
    const float* duv;
    const float* uv;
    if (in_sizes[0] == 2 * HW) { duv = a0; uv = a1; }
    else                        { duv = a1; uv = a0; }

    float* out = (float*)d_out;
    float* outDef  = out;
    float* outMask = out + NBATCH * HW * 2;

    const int SMBYTES = 12288 * (int)sizeof(float);
    cudaFuncSetAttribute(solve_kernel,
                         cudaFuncAttributeMaxDynamicSharedMemorySize, SMBYTES);

    warp_kernel<<<(NBATCH * HW + 255) / 256, 256>>>(duv, uv, outMask);
    solve_kernel<<<144, NTH, SMBYTES>>>();
    eval_kernel<<<dim3(HW / 256, NBATCH), 256>>>(outDef);
}

// round 9
// speedup vs baseline: 1.8105x; 1.0475x over previous
#include <cuda_runtime.h>
#include <math.h>

#define HH 192
#define WW 192
#define HW (HH*WW)
#define NBATCH 6
#define KC 400
#define MM 403
#define NCOL 405
#define SRIDE 416
#define LAMBDAV 100.0f
#define BIGV 1.0e8f
#define EPSV 1.0e-9f
#define STEPC (2.0f/191.0f)
#define HALF_LN2 0.34657359028f
#define NTH 512
#define NPAN 7
#define SDS 68                   // sD stride (16B-aligned 8-col groups)

// ---------------- device scratch ----------------
__device__ float g_A[NBATCH * MM * SRIDE];
__device__ float g_warp[NBATCH * 5 * HW];
__device__ float g_src[NBATCH * KC * 2];
__device__ float g_sol[NBATCH * MM * 2];
__device__ unsigned g_buildcnt[NBATCH];
__device__ unsigned g_panelflag[NBATCH];
__device__ unsigned g_prog[NBATCH * 8];
__device__ unsigned g_uready[NBATCH];
__device__ unsigned g_pdone[NBATCH];

__device__ __forceinline__ unsigned ldv(unsigned* p) { return *(volatile unsigned*)p; }

// ---------------- Stage 1: backward warp (+ flag reset) ----------------
__global__ void warp_kernel(const float* __restrict__ duv,
                            const float* __restrict__ uv,
                            float* __restrict__ outMask)
{
    if (blockIdx.x == 0) {
        if (threadIdx.x < NBATCH) {
            g_buildcnt[threadIdx.x] = 0;
            g_panelflag[threadIdx.x] = 0;
            g_uready[threadIdx.x] = 0;
            g_pdone[threadIdx.x] = 0;
        }
        if (threadIdx.x < NBATCH * 8) g_prog[threadIdx.x] = 0;
    }

    int idx = blockIdx.x * blockDim.x + threadIdx.x;
    if (idx >= NBATCH * HW) return;
    int n = idx / HW;
    int p = idx - n * HW;

    float u = uv[idx * 2 + 0];
    float v = uv[idx * 2 + 1];
    float x = (u + 1.0f) * 0.5f * (float)(WW - 1);
    float y = (v + 1.0f) * 0.5f * (float)(HH - 1);
    float x0f = floorf(x), y0f = floorf(y);
    float wx = x - x0f, wy = y - y0f;
    int x0 = (int)x0f, y0 = (int)y0f;

    float w00 = (1.0f - wx) * (1.0f - wy);
    float w10 = wx * (1.0f - wy);
    float w01 = (1.0f - wx) * wy;
    float w11 = wx * wy;

    float acc0 = 0.f, acc1 = 0.f, acc2 = 0.f, acc3 = 0.f, acc4 = 0.f;

    const int dxs[4] = {0, 1, 0, 1};
    const int dys[4] = {0, 0, 1, 1};
    const float wts[4] = {w00, w10, w01, w11};

    #pragma unroll
    for (int c = 0; c < 4; ++c) {
        int xi = x0 + dxs[c];
        int yi = y0 + dys[c];
        if (xi >= 0 && xi < WW && yi >= 0 && yi < HH) {
            int q = yi * WW + xi;
            float dux = duv[q * 2 + 0];
            float duy = duv[q * 2 + 1];
            float val = (fabsf(dux) <= 1.0f && fabsf(duy) <= 1.0f) ? 1.0f : 0.0f;
            float gx = xi * STEPC - 1.0f;
            float gy = yi * STEPC - 1.0f;
            float w = wts[c];
            acc0 += gx * w;
            acc1 += gy * w;
            acc2 += (dux - gx) * val * w;
            acc3 += (duy - gy) * val * w;
            acc4 += val * w;
        }
    }

    float mk = (acc4 > 0.5f) ? 1.0f : 0.0f;
    float* Wp = g_warp + n * 5 * HW;
    Wp[0 * HW + p] = acc0;
    Wp[1 * HW + p] = acc1;
    Wp[2 * HW + p] = acc2;
    Wp[3 * HW + p] = acc3;
    Wp[4 * HW + p] = mk;
    outMask[idx] = mk;
}

#define ACC4(acc, aa, bb) \
    acc.x = fmaf(aa, bb.x, acc.x); acc.y = fmaf(aa, bb.y, acc.y); \
    acc.z = fmaf(aa, bb.z, acc.z); acc.w = fmaf(aa, bb.w, acc.w);

// ---------------- shared GEMM tail: A[rows, col0..col0+w) -= L21 * Bs ----------------
__device__ void gemm_tiles(float* A, int k0, int col0, int w,
                           int rowStart, int rowStride,
                           const float* Bs, float* As, int tid)
{
    int c4 = (tid & 15) * 4;
    int r0 = (tid >> 4) * 2;
    int r1 = r0 + 1;
    for (int row0 = rowStart; row0 < MM; row0 += rowStride) {
        int nrows = MM - row0; if (nrows > 64) nrows = 64;
        for (int idx = tid; idx < 4096; idx += NTH) {
            int r = idx >> 6, c = idx & 63;
            As[idx] = (r < nrows) ? A[(row0 + r) * SRIDE + k0 + c] : 0.0f;
        }
        __syncthreads();

        float4 acc0 = {0.f,0.f,0.f,0.f};
        float4 acc1 = {0.f,0.f,0.f,0.f};
        #pragma unroll
        for (int kk4 = 0; kk4 < 16; ++kk4) {
            float4 a0 = *(const float4*)&As[r0 * 64 + kk4 * 4];
            float4 a1 = *(const float4*)&As[r1 * 64 + kk4 * 4];
            const float* bb = &Bs[(kk4 * 4) * 64 + c4];
            float4 b0 = *(const float4*)(bb);
            float4 b1 = *(const float4*)(bb + 64);
            float4 b2 = *(const float4*)(bb + 128);
            float4 b3 = *(const float4*)(bb + 192);
            ACC4(acc0, a0.x, b0) ACC4(acc0, a0.y, b1) ACC4(acc0, a0.z, b2) ACC4(acc0, a0.w, b3)
            ACC4(acc1, a1.x, b0) ACC4(acc1, a1.y, b1) ACC4(acc1, a1.z, b2) ACC4(acc1, a1.w, b3)
        }

        if (w == 64) {
            if (r0 < nrows) {
                float4 v = *(float4*)&A[(row0 + r0) * SRIDE + col0 + c4];
                v.x -= acc0.x; v.y -= acc0.y; v.z -= acc0.z; v.w -= acc0.w;
                *(float4*)&A[(row0 + r0) * SRIDE + col0 + c4] = v;
            }
            if (r1 < nrows) {
                float4 v = *(float4*)&A[(row0 + r1) * SRIDE + col0 + c4];
                v.x -= acc1.x; v.y -= acc1.y; v.z -= acc1.z; v.w -= acc1.w;
                *(float4*)&A[(row0 + r1) * SRIDE + col0 + c4] = v;
            }
        } else {
            float a0a[4] = {acc0.x, acc0.y, acc0.z, acc0.w};
            float a1a[4] = {acc1.x, acc1.y, acc1.z, acc1.w};
            #pragma unroll
            for (int q = 0; q < 4; ++q) {
                int c = c4 + q;
                if (c < w) {
                    if (r0 < nrows) A[(row0 + r0) * SRIDE + col0 + c] -= a0a[q];
                    if (r1 < nrows) A[(row0 + r1) * SRIDE + col0 + c] -= a1a[q];
                }
            }
        }
        __syncthreads();
    }
}

// ---------------- slab half: trisolve (8x8 blocked, sL stride 64) + GEMM ----------------
__device__ void slab_update_half(float* A, int j, int B, int parity, bool storeU, int tid)
{
    extern __shared__ float smdyn[];
    float* sL = smdyn;            // 64x64
    float* Bs = smdyn + 4096;     // 64x64
    float* As = smdyn + 8192;     // 64x64

    int k0 = 64 * j;
    int col0 = 64 * B;
    int w = NCOL - col0; if (w > 64) w = 64;
    int lo = k0 + 64;

    if (!storeU && lo + 64 * parity >= MM) return;

    for (int idx = tid; idx < 4096; idx += NTH) {
        int r = idx >> 6, c = idx & 63;
        sL[idx] = A[(k0 + r) * SRIDE + k0 + c];
        Bs[idx] = (c < w) ? A[(k0 + r) * SRIDE + col0 + c] : 0.0f;
    }
    __syncthreads();

    #pragma unroll
    for (int ib = 0; ib < 8; ++ib) {
        int base = ib * 8;
        if (tid < 64) {
            int c = tid;
            float x[8];
            #pragma unroll
            for (int r = 0; r < 8; ++r) x[r] = Bs[(base + r) * 64 + c];
            #pragma unroll
            for (int i = 0; i < 8; ++i) {
                float xi = x[i];
                #pragma unroll
                for (int r = 0; r < 8; ++r)
                    if (r > i) x[r] = fmaf(-sL[(base + r) * 64 + base + i], xi, x[r]);
            }
            #pragma unroll
            for (int r = 1; r < 8; ++r) Bs[(base + r) * 64 + c] = x[r];
        }
        __syncthreads();
        if (base + 8 < 64) {
            int c = tid & 63;
            int g = tid >> 6;
            for (int jj = base + 8 + g; jj < 64; jj += 8) {
                float acc = Bs[jj * 64 + c];
                #pragma unroll
                for (int i = 0; i < 8; ++i)
                    acc = fmaf(-sL[jj * 64 + base + i], Bs[(base + i) * 64 + c], acc);
                Bs[jj * 64 + c] = acc;
            }
        }
        __syncthreads();
    }

    if (storeU) {
        for (int idx = tid; idx < 4096; idx += NTH) {
            int r = idx >> 6, c = idx & 63;
            if (c < w) A[(k0 + r) * SRIDE + col0 + c] = Bs[idx];
        }
        __syncthreads();
    }

    gemm_tiles(A, k0, col0, w, lo + 64 * parity, 128, Bs, As, tid);
}

// ---------------- team: panel p0 trisolve+store; Bs prepared in panel smem ----------------
__device__ void team_trisolve_store(float* A, int k, int tid)
{
    extern __shared__ float smdyn[];
    float* sD = smdyn;            // stride SDS, panel k's factored diag (unit-lower L)
    float* Bs = smdyn + 4416;

    int k0 = 64 * k;
    int col0 = 64 * (k + 1);
    int w = NCOL - col0; if (w > 64) w = 64;

    for (int idx = tid; idx < 4096; idx += NTH) {
        int r = idx >> 6, c = idx & 63;
        Bs[idx] = (c < w) ? A[(k0 + r) * SRIDE + col0 + c] : 0.0f;
    }
    __syncthreads();

    #pragma unroll
    for (int ib = 0; ib < 8; ++ib) {
        int base = ib * 8;
        if (tid < 64) {
            int c = tid;
            float x[8];
            #pragma unroll
            for (int r = 0; r < 8; ++r) x[r] = Bs[(base + r) * 64 + c];
            #pragma unroll
            for (int i = 0; i < 8; ++i) {
                float xi = x[i];
                #pragma unroll
                for (int r = 0; r < 8; ++r)
                    if (r > i) x[r] = fmaf(-sD[(base + r) * SDS + base + i], xi, x[r]);
            }
            #pragma unroll
            for (int r = 1; r < 8; ++r) Bs[(base + r) * 64 + c] = x[r];
        }
        __syncthreads();
        if (base + 8 < 64) {
            int c = tid & 63;
            int g = tid >> 6;
            for (int jj = base + 8 + g; jj < 64; jj += 8) {
                float acc = Bs[jj * 64 + c];
                #pragma unroll
                for (int i = 0; i < 8; ++i)
                    acc = fmaf(-sD[jj * SDS + base + i], Bs[(base + i) * 64 + c], acc);
                Bs[jj * 64 + c] = acc;
            }
        }
        __syncthreads();
    }

    for (int idx = tid; idx < 4096; idx += NTH) {
        int r = idx >> 6, c = idx & 63;
        if (c < w) A[(k0 + r) * SRIDE + col0 + c] = Bs[idx];
    }
}

// ---------------- solver ----------------
__global__ void __launch_bounds__(NTH, 1) solve_kernel()
{
    extern __shared__ float smdyn[];
    int cta = blockIdx.x;
    int tid = threadIdx.x;
    int lane = tid & 31;
    int wid = tid >> 5;

    // ===== build: 144 CTAs, 24 per matrix =====
    {
        int n = cta % NBATCH;
        int part = cta / NBATCH;
        float* s_sx = smdyn;
        float* s_sy = smdyn + KC;
        float* s_m  = smdyn + 2 * KC;
        float* s_dx = smdyn + 3 * KC;
        float* s_dy = smdyn + 4 * KC;

        const float* Wp = g_warp + n * 5 * HW;
        for (int k = tid; k < KC; k += NTH) {
            int a = k / 20, b = k - a * 20;
            int ii = __double2int_rn(a * (191.0 / 19.0));
            int jj = __double2int_rn(b * (191.0 / 19.0));
            int p = ii * WW + jj;
            float sx = Wp[p];
            float sy = Wp[HW + p];
            float m  = Wp[4 * HW + p];
            s_sx[k] = sx; s_sy[k] = sy; s_m[k] = m;
            s_dx[k] = jj * STEPC - 1.0f;
            s_dy[k] = ii * STEPC - 1.0f;
            if (part == 0) {
                g_src[(n * KC + k) * 2 + 0] = sx;
                g_src[(n * KC + k) * 2 + 1] = sy;
            }
        }
        __syncthreads();

        float* A = g_A + n * MM * SRIDE;
        int r0 = part * 17;
        int r1 = min(MM, r0 + 17);
        for (int i = r0; i < r1; ++i) {
            for (int j = tid; j < NCOL; j += NTH) {
                float vout;
                if (i < KC) {
                    if (j < KC) {
                        float dx = s_sx[i] - s_sx[j];
                        float dy = s_sy[i] - s_sy[j];
                        float r2 = dx * dx + dy * dy;
                        vout = 0.5f * r2 * __logf(r2 + EPSV);
                        if (i == j) vout += LAMBDAV + BIGV * (1.0f - s_m[i]);
                    } else if (j == 400) vout = 1.0f;
                    else if (j == 401) vout = s_sx[i];
                    else if (j == 402) vout = s_sy[i];
                    else if (j == 403) vout = s_dx[i];
                    else               vout = s_dy[i];
                } else {
                    if (j < KC) {
                        vout = (i == 400) ? 1.0f : ((i == 401) ? s_sx[j] : s_sy[j]);
                    } else {
                        vout = 0.0f;
                    }
                }
                A[i * SRIDE + j] = vout;
            }
        }
        __threadfence();
        __syncthreads();
        if (tid == 0) atomicAdd(&g_buildcnt[n], 1u);
    }
    if (cta >= 84) return;
    __syncthreads();

    // ===== slab half CTAs: 24..83 =====
    if (cta >= 24) {
        int idx = cta - 24;
        int n = idx / 10;
        int rem = idx - n * 10;
        int B = 2 + rem / 2;
        int h = rem & 1;
        float* A = g_A + n * MM * SRIDE;
        for (int j = 0; j <= B - 2; ++j) {
            if (tid == 0) {
                while (ldv(&g_panelflag[n]) < (unsigned)(j + 1)) __nanosleep(64);
                while (ldv(&g_prog[n * 8 + B]) < (unsigned)(2 * j)) __nanosleep(64);
            }
            __syncthreads();
            __threadfence();
            slab_update_half(A, j, B, h, h == 0, tid);
            __threadfence();
            __syncthreads();
            if (tid == 0) atomicAdd(&g_prog[n * 8 + B], 1u);
        }
        return;
    }

    // ===== partner CTAs: 6..23 (3 per matrix, quarters p=1..3) =====
    if (cta >= NBATCH) {
        int n = (cta - NBATCH) / 3;
        int p = 1 + (cta - NBATCH) % 3;
        float* A = g_A + n * MM * SRIDE;
        float* Bs = smdyn + 4416;
        float* As = smdyn + 8512;
        for (int k = 0; k < NPAN - 1; ++k) {
            if (tid == 0) { while (ldv(&g_uready[n]) < (unsigned)(k + 1)) __nanosleep(64); }
            __syncthreads();
            __threadfence();
            int col0 = 64 * (k + 1);
            int rowStart = col0 + 64 * p;
            if (rowStart < MM) {
                int w = NCOL - col0; if (w > 64) w = 64;
                int k0 = 64 * k;
                for (int idx = tid; idx < 4096; idx += NTH) {
                    int r = idx >> 6, c = idx & 63;
                    Bs[idx] = (c < w) ? A[(k0 + r) * SRIDE + col0 + c] : 0.0f;
                }
                __syncthreads();
                gemm_tiles(A, k0, col0, w, rowStart, 256, Bs, As, tid);
                __threadfence();
            }
            __syncthreads();
            if (tid == 0) atomicAdd(&g_pdone[n], 1u);
        }
        return;
    }

    // ===== panel CTAs: 0..5 =====
    int n = cta;
    float* A = g_A + n * MM * SRIDE;

    if (tid == 0) { while (ldv(&g_buildcnt[n]) < 24u) __nanosleep(64); }
    __syncthreads();
    __threadfence();

    float* sD    = smdyn;             // 64 x SDS
    float* sdinv = smdyn + 4352;      // 64
    float* BsT   = smdyn + 4416;
    float* AsT   = smdyn + 8512;

    for (int k = 0; k < NPAN; ++k) {
        int k0 = 64 * k;
        int nb = MM - k0; if (nb > 64) nb = 64;
        int R  = MM - k0;

        // ---- diag block factorization in smem (stride SDS) ----
        for (int idx = tid; idx < nb * nb; idx += NTH) {
            int r = idx / nb, c = idx - r * nb;
            sD[r * SDS + c] = A[(k0 + r) * SRIDE + k0 + c];
        }
        __syncthreads();

        for (int j = 0; j < nb - 1; ++j) {
            if (tid > j && tid < nb) {
                float m = sD[tid * SDS + j] * __fdividef(1.0f, sD[j * SDS + j]);
                sD[tid * SDS + j] = m;
            }
            __syncthreads();
            {
                int r = tid & 63;
                int cg = tid >> 6;
                if (r > j && r < nb) {
                    float m = sD[r * SDS + j];
                    for (int c = j + 1 + cg; c < nb; c += 8)
                        sD[r * SDS + c] = fmaf(-m, sD[j * SDS + c], sD[r * SDS + c]);
                }
            }
            __syncthreads();
        }

        if (tid < nb) sdinv[tid] = __fdividef(1.0f, sD[tid * SDS + tid]);
        for (int idx = tid; idx < nb * nb; idx += NTH) {
            int r = idx / nb, c = idx - r * nb;
            A[(k0 + r) * SRIDE + k0 + c] = sD[r * SDS + c];
        }
        __syncthreads();

        // ---- L21 = A21 * U11^-1, per-thread rows, float4 U broadcasts ----
        if (nb == 64 && tid < R - 64) {
            float* rowp = A + (k0 + 64 + tid) * SRIDE + k0;
            #pragma unroll 1
            for (int jb = 0; jb < 8; ++jb) {
                int J0 = jb * 8;
                float x[8];
                {
                    float4 v0 = *(const float4*)&rowp[J0];
                    float4 v1 = *(const float4*)&rowp[J0 + 4];
                    x[0]=v0.x; x[1]=v0.y; x[2]=v0.z; x[3]=v0.w;
                    x[4]=v1.x; x[5]=v1.y; x[6]=v1.z; x[7]=v1.w;
                }
                for (int i = 0; i < J0; ++i) {
                    float li = rowp[i];
                    float4 u0 = *(const float4*)&sD[i * SDS + J0];
                    float4 u1 = *(const float4*)&sD[i * SDS + J0 + 4];
                    x[0] = fmaf(-li, u0.x, x[0]); x[1] = fmaf(-li, u0.y, x[1]);
                    x[2] = fmaf(-li, u0.z, x[2]); x[3] = fmaf(-li, u0.w, x[3]);
                    x[4] = fmaf(-li, u1.x, x[4]); x[5] = fmaf(-li, u1.y, x[5]);
                    x[6] = fmaf(-li, u1.z, x[6]); x[7] = fmaf(-li, u1.w, x[7]);
                }
                #pragma unroll
                for (int i = 0; i < 8; ++i) {
                    float xi = x[i] * sdinv[J0 + i];
                    x[i] = xi;
                    const float* urow = &sD[(J0 + i) * SDS + J0];
                    #pragma unroll
                    for (int q = 0; q < 8; ++q)
                        if (q > i) x[q] = fmaf(-xi, urow[q], x[q]);
                }
                {
                    float4 v0 = {x[0], x[1], x[2], x[3]};
                    float4 v1 = {x[4], x[5], x[6], x[7]};
                    *(float4*)&rowp[J0] = v0;
                    *(float4*)&rowp[J0 + 4] = v1;
                }
            }
        }
        __threadfence();
        __syncthreads();
        if (tid == 0) atomicExch(&g_panelflag[n], (unsigned)(k + 1));

        if (k < NPAN - 1) {
            int Bb = k + 1;
            if (Bb >= 2) {
                if (tid == 0) { while (ldv(&g_prog[n * 8 + Bb]) < (unsigned)(2 * k)) __nanosleep(64); }
                __syncthreads();
                __threadfence();
            }
            // p0: trisolve block k+1 against sD, store U12, publish
            team_trisolve_store(A, k, tid);
            __threadfence();
            __syncthreads();
            if (tid == 0) atomicExch(&g_uready[n], (unsigned)(k + 1));
            // own quarter GEMM (p=0)
            {
                int col0 = 64 * (k + 1);
                int w = NCOL - col0; if (w > 64) w = 64;
                gemm_tiles(A, k0, col0, w, col0, 256, BsT, AsT, tid);
            }
            __syncthreads();
            if (tid == 0) { while (ldv(&g_pdone[n]) < (unsigned)(3 * (k + 1))) __nanosleep(64); }
            __syncthreads();
            __threadfence();
        } else {
            // RHS forward-solve (rows 384..402, cols 403/404) using sD (unit-lower L)
            if (tid < 2) {
                float x[19];
                float* colp = A + 384 * SRIDE + 403 + tid;
                #pragma unroll
                for (int r = 0; r < 19; ++r) x[r] = colp[r * SRIDE];
                #pragma unroll
                for (int i = 0; i < 19; ++i) {
                    float xi = x[i];
                    #pragma unroll
                    for (int jj = i + 1; jj < 19; ++jj)
                        x[jj] = fmaf(-sD[jj * SDS + i], xi, x[jj]);
                }
                #pragma unroll
                for (int r = 0; r < 19; ++r) colp[r * SRIDE] = x[r];
            }
            __syncthreads();
        }
    }

    // ===== back-substitution =====
    {
        float* sB  = smdyn;              // 64x65
        float* x0s = smdyn + 4416;       // MM
        float* x1s = x0s + MM;

        for (int j = tid; j < MM; j += NTH) {
            x0s[j] = A[j * SRIDE + 403];
            x1s[j] = A[j * SRIDE + 404];
        }
        __syncthreads();

        for (int b = 6; b >= 0; --b) {
            int bk0 = b * 64;
            int bnb = (MM - bk0 < 64) ? (MM - bk0) : 64;

            for (int idx = tid; idx < bnb * bnb; idx += NTH) {
                int r = idx / bnb, cc = idx - r * bnb;
                sB[r * 65 + cc] = A[(bk0 + r) * SRIDE + bk0 + cc];
            }
            __syncthreads();

            if (wid == 0) {
                for (int k = bnb - 1; k >= 0; --k) {
                    float s0 = 0.f, s1 = 0.f;
                    for (int j = k + 1 + lane; j < bnb; j += 32) {
                        float u = sB[k * 65 + j];
                        s0 = fmaf(u, x0s[bk0 + j], s0);
                        s1 = fmaf(u, x1s[bk0 + j], s1);
                    }
                    #pragma unroll
                    for (int off = 16; off > 0; off >>= 1) {
                        s0 += __shfl_down_sync(0xffffffffu, s0, off);
                        s1 += __shfl_down_sync(0xffffffffu, s1, off);
                    }
                    if (lane == 0) {
                        float d = 1.0f / sB[k * 65 + k];
                        x0s[bk0 + k] = (x0s[bk0 + k] - s0) * d;
                        x1s[bk0 + k] = (x1s[bk0 + k] - s1) * d;
                    }
                    __syncwarp();
                }
            }
            __syncthreads();

            for (int r = tid; r < bk0; r += NTH) {
                float s0 = 0.f, s1 = 0.f;
                const float* Ur = A + r * SRIDE + bk0;
                #pragma unroll 8
                for (int j = 0; j < bnb; ++j) {
                    float u = Ur[j];
                    s0 = fmaf(u, x0s[bk0 + j], s0);
                    s1 = fmaf(u, x1s[bk0 + j], s1);
                }
                x0s[r] -= s0;
                x1s[r] -= s1;
            }
            __syncthreads();
        }

        for (int j = tid; j < MM; j += NTH) {
            g_sol[(n * MM + j) * 2 + 0] = x0s[j];
            g_sol[(n * MM + j) * 2 + 1] = x1s[j];
        }
    }
}

// ---------------- Stage 4: TPS evaluation + Jacobian + output ----------------
__global__ void __launch_bounds__(256) eval_kernel(float* __restrict__ outDef)
{
    int n = blockIdx.y;
    int p = blockIdx.x * blockDim.x + threadIdx.x;
    int tid = threadIdx.x;

    __shared__ float4 s_sw[KC];
    __shared__ float s_aff[6];

    for (int k = tid; k < KC; k += blockDim.x) {
        float4 t;
        t.x = g_src[(n * KC + k) * 2 + 0];
        t.y = g_src[(n * KC + k) * 2 + 1];
        t.z = g_sol[(n * MM + k) * 2 + 0] * HALF_LN2;
        t.w = g_sol[(n * MM + k) * 2 + 1] * HALF_LN2;
        s_sw[k] = t;
    }
    if (tid < 6) s_aff[tid] = g_sol[(n * MM + 400) * 2 + tid];
    __syncthreads();

    const float* Wp = g_warp + n * 5 * HW;
    float q0x = Wp[p];
    float q0y = Wp[HW + p];
    float dlx = Wp[2 * HW + p];
    float dly = Wp[3 * HW + p];
    float mk  = Wp[4 * HW + p];

    float a0x = 0.f, a0y = 0.f, a1x = 0.f, a1y = 0.f, a2x = 0.f, a2y = 0.f;

    #pragma unroll 4
    for (int k = 0; k < KC; ++k) {
        float4 s = s_sw[k];
        float d0x = q0x - s.x;
        float d0y = q0y - s.y;
        float e0x = fmaf(2.0f, d0x, STEPC);
        float e0y = fmaf(2.0f, d0y, STEPC);
        float r0 = fmaf(d0x, d0x, d0y * d0y) + EPSV;
        float r1 = fmaf(STEPC, e0x, r0);
        float r2 = fmaf(STEPC, e0y, r0);
        float u0 = r0 * __log2f(r0);
        float u1 = r1 * __log2f(r1);
        float u2 = r2 * __log2f(r2);
        a0x = fmaf(u0, s.z, a0x);  a0y = fmaf(u0, s.w, a0y);
        a1x = fmaf(u1, s.z, a1x);  a1y = fmaf(u1, s.w, a1y);
        a2x = fmaf(u2, s.z, a2x);  a2y = fmaf(u2, s.w, a2y);
    }

    float q1x = q0x + STEPC;
    float q2y = q0y + STEPC;
    float c0x = a0x + s_aff[0] + s_aff[2] * q0x + s_aff[4] * q0y;
    float c0y = a0y + s_aff[1] + s_aff[3] * q0x + s_aff[5] * q0y;
    float c1x = a1x + s_aff[0] + s_aff[2] * q1x + s_aff[4] * q0y;
    float c1y = a1y + s_aff[1] + s_aff[3] * q1x + s_aff[5] * q0y;
    float c2x = a2x + s_aff[0] + s_aff[2] * q0x + s_aff[4] * q2y;
    float c2y = a2y + s_aff[1] + s_aff[3] * q0x + s_aff[5] * q2y;

    float ja = (c1x - c0x) / STEPC;
    float jb = (c1y - c0y) / STEPC;
    float jc = (c2x - c0x) / STEPC;
    float jd = (c2y - c0y) / STEPC;

    float dnx = ja * dlx + jc * dly;
    float dny = jb * dlx + jd * dly;

    int i = p / WW;
    int j = p - i * WW;
    float gx = j * STEPC - 1.0f;
    float gy = i * STEPC - 1.0f;
    float dfx = (gx + dnx) * mk - 2.0f * (1.0f - mk);
    float dfy = (gy + dny) * mk - 2.0f * (1.0f - mk);

    outDef[(n * HW + p) * 2 + 0] = dfx;
    outDef[(n * HW + p) * 2 + 1] = dfy;
}

// ---------------- launch ----------------
extern "C" void kernel_launch(void* const* d_in, const int* in_sizes, int n_in,
                              void* d_out, int out_size)
{
    const float* a0 = (const float*)d_in[0];
    const float* a1 = (const float*)d_in[1];
    const float* duv;
    const float* uv;
    if (in_sizes[0] == 2 * HW) { duv = a0; uv = a1; }
    else                        { duv = a1; uv = a0; }

    float* out = (float*)d_out;
    float* outDef  = out;
    float* outMask = out + NBATCH * HW * 2;

    const int SMBYTES = 12608 * (int)sizeof(float);   // ~50.4 KB dynamic
    cudaFuncSetAttribute(solve_kernel,
                         cudaFuncAttributeMaxDynamicSharedMemorySize, SMBYTES);

    warp_kernel<<<(NBATCH * HW + 255) / 256, 256>>>(duv, uv, outMask);
    solve_kernel<<<144, NTH, SMBYTES>>>();
    eval_kernel<<<dim3(HW / 256, NBATCH), 256>>>(outDef);
}